// round 2
// baseline (speedup 1.0000x reference)
#include <cuda_runtime.h>
#include <math.h>

// Problem constants
#define BB 8
#define NN 2048
#define DD 512
#define MTOT (BB * NN)   // 16384 rows

// Scratch (alloc-free rule: __device__ globals)
__device__ float g_Q[MTOT * DD];
__device__ float g_K[MTOT * DD];
__device__ float g_V[MTOT * DD];
__device__ float g_S[(size_t)BB * NN * NN];

// ---------------------------------------------------------------------------
// Tiled SGEMM cores: BM=BN=128, BK=8, TM=TN=8, 256 threads
// ---------------------------------------------------------------------------

// C-tile accum for C = A * B^T where A is [M,K] row-major and B is [N,K] row-major.
// blockIdx.y selects 128-row tile of A, blockIdx.x selects 128-row tile of B.
__device__ __forceinline__ void gemm_nt_tile(
    const float* __restrict__ A, const float* __restrict__ B,
    int K, float acc[8][8])
{
    __shared__ float As[8][128];
    __shared__ float Bs[8][128];
    const int tid  = threadIdx.x;
    const int lRow = tid >> 1;           // 0..127
    const int lCol = (tid & 1) << 2;     // 0 or 4
    const float* Ap = A + (size_t)((blockIdx.y << 7) + lRow) * K + lCol;
    const float* Bp = B + (size_t)((blockIdx.x << 7) + lRow) * K + lCol;
    const int tRow = (tid >> 4) << 3;    // 0..120
    const int tCol = (tid & 15) << 3;    // 0..120

    for (int k0 = 0; k0 < K; k0 += 8) {
        float4 a4 = *reinterpret_cast<const float4*>(Ap + k0);
        float4 b4 = *reinterpret_cast<const float4*>(Bp + k0);
        As[lCol + 0][lRow] = a4.x; As[lCol + 1][lRow] = a4.y;
        As[lCol + 2][lRow] = a4.z; As[lCol + 3][lRow] = a4.w;
        Bs[lCol + 0][lRow] = b4.x; Bs[lCol + 1][lRow] = b4.y;
        Bs[lCol + 2][lRow] = b4.z; Bs[lCol + 3][lRow] = b4.w;
        __syncthreads();
#pragma unroll
        for (int k = 0; k < 8; k++) {
            float ra[8], rb[8];
#pragma unroll
            for (int i = 0; i < 8; i++) ra[i] = As[k][tRow + i];
#pragma unroll
            for (int j = 0; j < 8; j++) rb[j] = Bs[k][tCol + j];
#pragma unroll
            for (int i = 0; i < 8; i++)
#pragma unroll
                for (int j = 0; j < 8; j++)
                    acc[i][j] = fmaf(ra[i], rb[j], acc[i][j]);
        }
        __syncthreads();
    }
}

// C-tile accum for C = A * B where A is [M,K] row-major and B is [K,N] row-major
// with leading dimension ldb (= N). blockIdx.x selects 128-col tile of B/C.
__device__ __forceinline__ void gemm_nn_tile(
    const float* __restrict__ A, const float* __restrict__ B,
    int K, int ldb, float acc[8][8])
{
    __shared__ float As[8][128];
    __shared__ float Bs[8][128];
    const int tid  = threadIdx.x;
    const int aRow = tid >> 1;
    const int aCol = (tid & 1) << 2;
    const float* Ap = A + (size_t)((blockIdx.y << 7) + aRow) * K + aCol;
    const int bRow = tid >> 5;           // 0..7
    const int bCol = (tid & 31) << 2;    // 0..124
    const float* Bp = B + (size_t)bRow * ldb + (blockIdx.x << 7) + bCol;
    const int tRow = (tid >> 4) << 3;
    const int tCol = (tid & 15) << 3;

    for (int k0 = 0; k0 < K; k0 += 8) {
        float4 a4 = *reinterpret_cast<const float4*>(Ap + k0);
        float4 b4 = *reinterpret_cast<const float4*>(Bp + (size_t)k0 * ldb);
        As[aCol + 0][aRow] = a4.x; As[aCol + 1][aRow] = a4.y;
        As[aCol + 2][aRow] = a4.z; As[aCol + 3][aRow] = a4.w;
        *reinterpret_cast<float4*>(&Bs[bRow][bCol]) = b4;
        __syncthreads();
#pragma unroll
        for (int k = 0; k < 8; k++) {
            float ra[8], rb[8];
#pragma unroll
            for (int i = 0; i < 8; i++) ra[i] = As[k][tRow + i];
#pragma unroll
            for (int j = 0; j < 8; j++) rb[j] = Bs[k][tCol + j];
#pragma unroll
            for (int i = 0; i < 8; i++)
#pragma unroll
                for (int j = 0; j < 8; j++)
                    acc[i][j] = fmaf(ra[i], rb[j], acc[i][j]);
        }
        __syncthreads();
    }
}

// ---------------------------------------------------------------------------
// Kernel 1: QKV projections. y = x @ W^T + b (torch Linear convention).
// grid = (DD/128, MTOT/128, 3); z: 0->Q, 1->K, 2->V.
// ---------------------------------------------------------------------------
__global__ __launch_bounds__(256) void proj_kernel(
    const float* __restrict__ X,
    const float* __restrict__ Wq, const float* __restrict__ bq,
    const float* __restrict__ Wk, const float* __restrict__ bk,
    const float* __restrict__ Wv, const float* __restrict__ bv)
{
    const float* W; const float* bias; float* C;
    if (blockIdx.z == 0)      { W = Wq; bias = bq; C = g_Q; }
    else if (blockIdx.z == 1) { W = Wk; bias = bk; C = g_K; }
    else                      { W = Wv; bias = bv; C = g_V; }

    float acc[8][8];
#pragma unroll
    for (int i = 0; i < 8; i++)
#pragma unroll
        for (int j = 0; j < 8; j++) acc[i][j] = 0.f;

    gemm_nt_tile(X, W, DD, acc);

    const int tid  = threadIdx.x;
    const int tRow = (tid >> 4) << 3;
    const int tCol = (tid & 15) << 3;
    const int rowBase = (blockIdx.y << 7) + tRow;
    const int colBase = (blockIdx.x << 7) + tCol;
#pragma unroll
    for (int i = 0; i < 8; i++) {
        float* cp = C + (size_t)(rowBase + i) * DD + colBase;
#pragma unroll
        for (int j = 0; j < 8; j++)
            cp[j] = acc[i][j] + bias[colBase + j];
    }
}

// ---------------------------------------------------------------------------
// Kernel 2: scores S[b,q,k] = (Q[b,q,:] . K[b,k,:]) / sqrt(D), masked.
// grid = (NN/128, NN/128, BB)
// ---------------------------------------------------------------------------
__global__ __launch_bounds__(256) void scores_kernel(const int* __restrict__ mask)
{
    const int b = blockIdx.z;
    const float* A = g_Q + (size_t)b * NN * DD;
    const float* B = g_K + (size_t)b * NN * DD;
    float* C = g_S + (size_t)b * NN * NN;

    float acc[8][8];
#pragma unroll
    for (int i = 0; i < 8; i++)
#pragma unroll
        for (int j = 0; j < 8; j++) acc[i][j] = 0.f;

    gemm_nt_tile(A, B, DD, acc);

    const float scale = 1.0f / 22.62741699796952f;  // 1/sqrt(512)
    const int tid  = threadIdx.x;
    const int tRow = (tid >> 4) << 3;
    const int tCol = (tid & 15) << 3;
    const int rowBase = (blockIdx.y << 7) + tRow;
    const int colBase = (blockIdx.x << 7) + tCol;
    const int* mrow = mask + (size_t)b * NN;
    float madd[8];
#pragma unroll
    for (int j = 0; j < 8; j++)
        madd[j] = (mrow[colBase + j] == 0) ? 1.0f : 0.0f;  // 1 => masked
#pragma unroll
    for (int i = 0; i < 8; i++) {
        float* cp = C + (size_t)(rowBase + i) * NN + colBase;
#pragma unroll
        for (int j = 0; j < 8; j++) {
            float v = acc[i][j] * scale;
            cp[j] = (madd[j] != 0.0f) ? -1e9f : v;
        }
    }
}

// ---------------------------------------------------------------------------
// Kernel 3: in-place row softmax over NN=2048 elements. One block per row.
// ---------------------------------------------------------------------------
__global__ __launch_bounds__(256) void softmax_kernel()
{
    __shared__ float sred[8];
    float* r = g_S + (size_t)blockIdx.x * NN;
    const int tid = threadIdx.x;

    float v[8];
    float m = -INFINITY;
#pragma unroll
    for (int t = 0; t < 8; t++) {
        v[t] = r[tid + t * 256];
        m = fmaxf(m, v[t]);
    }
#pragma unroll
    for (int off = 16; off > 0; off >>= 1)
        m = fmaxf(m, __shfl_xor_sync(0xffffffffu, m, off));
    if ((tid & 31) == 0) sred[tid >> 5] = m;
    __syncthreads();
    m = sred[0];
#pragma unroll
    for (int w = 1; w < 8; w++) m = fmaxf(m, sred[w]);

    float s = 0.f;
#pragma unroll
    for (int t = 0; t < 8; t++) {
        v[t] = __expf(v[t] - m);
        s += v[t];
    }
#pragma unroll
    for (int off = 16; off > 0; off >>= 1)
        s += __shfl_xor_sync(0xffffffffu, s, off);
    __syncthreads();  // all reads of sred (max) done before reuse
    if ((tid & 31) == 0) sred[tid >> 5] = s;
    __syncthreads();
    s = 0.f;
#pragma unroll
    for (int w = 0; w < 8; w++) s += sred[w];
    const float inv = 1.0f / s;
#pragma unroll
    for (int t = 0; t < 8; t++)
        r[tid + t * 256] = v[t] * inv;
}

// ---------------------------------------------------------------------------
// Kernel 4: O[b,q,d] = sum_k P[b,q,k] * V[b,k,d].  grid = (DD/128, NN/128, BB)
// ---------------------------------------------------------------------------
__global__ __launch_bounds__(256) void av_kernel(float* __restrict__ out)
{
    const int b = blockIdx.z;
    const float* A = g_S + (size_t)b * NN * NN;   // [NN, NN]
    const float* B = g_V + (size_t)b * NN * DD;   // [NN, DD]
    float* C = out + (size_t)b * NN * DD;

    float acc[8][8];
#pragma unroll
    for (int i = 0; i < 8; i++)
#pragma unroll
        for (int j = 0; j < 8; j++) acc[i][j] = 0.f;

    gemm_nn_tile(A, B, NN, DD, acc);

    const int tid  = threadIdx.x;
    const int tRow = (tid >> 4) << 3;
    const int tCol = (tid & 15) << 3;
    const int rowBase = (blockIdx.y << 7) + tRow;
    const int colBase = (blockIdx.x << 7) + tCol;
#pragma unroll
    for (int i = 0; i < 8; i++) {
        float* cp = C + (size_t)(rowBase + i) * DD + colBase;
#pragma unroll
        for (int j = 0; j < 4; j++) {
            // two float4 stores per row
        }
        float4 s0 = make_float4(acc[i][0], acc[i][1], acc[i][2], acc[i][3]);
        float4 s1 = make_float4(acc[i][4], acc[i][5], acc[i][6], acc[i][7]);
        *reinterpret_cast<float4*>(cp + 0) = s0;
        *reinterpret_cast<float4*>(cp + 4) = s1;
    }
}

// ---------------------------------------------------------------------------
// Launch
// ---------------------------------------------------------------------------
extern "C" void kernel_launch(void* const* d_in, const int* in_sizes, int n_in,
                              void* d_out, int out_size)
{
    const float* X    = (const float*)d_in[0];
    const int*   mask = (const int*)  d_in[1];
    const float* Wk   = (const float*)d_in[2];
    const float* bk   = (const float*)d_in[3];
    const float* Wq   = (const float*)d_in[4];
    const float* bq   = (const float*)d_in[5];
    const float* Wv   = (const float*)d_in[6];
    const float* bv   = (const float*)d_in[7];
    float* out = (float*)d_out;

    proj_kernel  <<<dim3(DD / 128, MTOT / 128, 3), 256>>>(X, Wq, bq, Wk, bk, Wv, bv);
    scores_kernel<<<dim3(NN / 128, NN / 128, BB), 256>>>(mask);
    softmax_kernel<<<MTOT, 256>>>();
    av_kernel    <<<dim3(DD / 128, NN / 128, BB), 256>>>(out);
}

// round 3
// speedup vs baseline: 3.1273x; 3.1273x over previous
#include <cuda_runtime.h>
#include <math.h>

#define BB 8
#define NSEQ 2048
#define DIM 512
#define MTOT (BB * NSEQ)

// Scratch (alloc-free rule: __device__ globals)
__device__ float g_Q[(size_t)MTOT * DIM];
__device__ float g_K[(size_t)MTOT * DIM];
__device__ float g_V[(size_t)MTOT * DIM];
__device__ float g_S[(size_t)BB * NSEQ * NSEQ];

// ---------------------------------------------------------------------------
// tf32 helpers
// ---------------------------------------------------------------------------
__device__ __forceinline__ unsigned f2tf(float x) {
    unsigned u;
    asm("cvt.rna.tf32.f32 %0, %1;" : "=r"(u) : "f"(x));
    return u;
}

__device__ __forceinline__ void mma8(float c[4],
                                     unsigned a0, unsigned a1, unsigned a2, unsigned a3,
                                     unsigned b0, unsigned b1) {
    asm volatile(
        "mma.sync.aligned.m16n8k8.row.col.f32.tf32.tf32.f32 "
        "{%0,%1,%2,%3}, {%4,%5,%6,%7}, {%8,%9}, {%0,%1,%2,%3};"
        : "+f"(c[0]), "+f"(c[1]), "+f"(c[2]), "+f"(c[3])
        : "r"(a0), "r"(a1), "r"(a2), "r"(a3), "r"(b0), "r"(b1));
}

// ---------------------------------------------------------------------------
// Fragment compute for one 128x128x16 smem tile.
// As: [128][20] row-major (m, k). Bs_nt: [128][20] (n, k). Bs_nn: [16][136] (k, n).
// Warp tile 64x32: 4 m-frags (16) x 4 n-frags (8), 2 k-steps of 8.
// ---------------------------------------------------------------------------
__device__ __forceinline__ void compute_tile_nt(
    const unsigned (*As)[20], const unsigned (*Bs)[20],
    int wm, int wn, int grp, int tig, float acc[4][4][4])
{
#pragma unroll
    for (int ks = 0; ks < 2; ks++) {
        unsigned af[4][4], bf[4][2];
        const int k = ks * 8 + tig;
#pragma unroll
        for (int i = 0; i < 4; i++) {
            const int r = wm + i * 16 + grp;
            af[i][0] = As[r][k];
            af[i][1] = As[r + 8][k];
            af[i][2] = As[r][k + 4];
            af[i][3] = As[r + 8][k + 4];
        }
#pragma unroll
        for (int j = 0; j < 4; j++) {
            const int c = wn + j * 8 + grp;
            bf[j][0] = Bs[c][k];
            bf[j][1] = Bs[c][k + 4];
        }
#pragma unroll
        for (int i = 0; i < 4; i++)
#pragma unroll
            for (int j = 0; j < 4; j++)
                mma8(acc[i][j], af[i][0], af[i][1], af[i][2], af[i][3],
                     bf[j][0], bf[j][1]);
    }
}

__device__ __forceinline__ void compute_tile_nn(
    const unsigned (*As)[20], const unsigned (*Bs)[136],
    int wm, int wn, int grp, int tig, float acc[4][4][4])
{
#pragma unroll
    for (int ks = 0; ks < 2; ks++) {
        unsigned af[4][4], bf[4][2];
        const int k = ks * 8 + tig;
#pragma unroll
        for (int i = 0; i < 4; i++) {
            const int r = wm + i * 16 + grp;
            af[i][0] = As[r][k];
            af[i][1] = As[r + 8][k];
            af[i][2] = As[r][k + 4];
            af[i][3] = As[r + 8][k + 4];
        }
#pragma unroll
        for (int j = 0; j < 4; j++) {
            const int c = wn + j * 8 + grp;
            bf[j][0] = Bs[k][c];
            bf[j][1] = Bs[k + 4][c];
        }
#pragma unroll
        for (int i = 0; i < 4; i++)
#pragma unroll
            for (int j = 0; j < 4; j++)
                mma8(acc[i][j], af[i][0], af[i][1], af[i][2], af[i][3],
                     bf[j][0], bf[j][1]);
    }
}

// ---------------------------------------------------------------------------
// NT mainloop: C(128x128 at (by,bx)) += A[M,K] * B[N,K]^T, double buffered.
// ---------------------------------------------------------------------------
__device__ __forceinline__ void gemm_nt_main(
    const float* __restrict__ A, const float* __restrict__ B,
    int lda, int ldb, int ktiles, float acc[4][4][4])
{
    __shared__ unsigned As[2][128][20];
    __shared__ unsigned Bs[2][128][20];

    const int tid = threadIdx.x;
    const int r0  = tid >> 2;            // 0..63
    const int kq  = (tid & 3) << 2;      // 0,4,8,12
    const float* Ap = A + (size_t)(blockIdx.y * 128 + r0) * lda + kq;
    const float* Bp = B + (size_t)(blockIdx.x * 128 + r0) * ldb + kq;
    const size_t a64 = (size_t)64 * lda;
    const size_t b64 = (size_t)64 * ldb;

    float4 ra0 = *(const float4*)(Ap);
    float4 ra1 = *(const float4*)(Ap + a64);
    float4 rb0 = *(const float4*)(Bp);
    float4 rb1 = *(const float4*)(Bp + b64);
    *(uint4*)&As[0][r0     ][kq] = make_uint4(f2tf(ra0.x), f2tf(ra0.y), f2tf(ra0.z), f2tf(ra0.w));
    *(uint4*)&As[0][r0 + 64][kq] = make_uint4(f2tf(ra1.x), f2tf(ra1.y), f2tf(ra1.z), f2tf(ra1.w));
    *(uint4*)&Bs[0][r0     ][kq] = make_uint4(f2tf(rb0.x), f2tf(rb0.y), f2tf(rb0.z), f2tf(rb0.w));
    *(uint4*)&Bs[0][r0 + 64][kq] = make_uint4(f2tf(rb1.x), f2tf(rb1.y), f2tf(rb1.z), f2tf(rb1.w));
    __syncthreads();

    const int lane = tid & 31;
    const int warp = tid >> 5;
    const int wm  = (warp >> 2) * 64;
    const int wn  = (warp & 3) * 32;
    const int grp = lane >> 2;
    const int tig = lane & 3;

#pragma unroll 1
    for (int kt = 0; kt < ktiles; kt++) {
        const int buf = kt & 1;
        const bool pf = (kt + 1 < ktiles);
        if (pf) {
            const float* Ap2 = Ap + (kt + 1) * 16;
            const float* Bp2 = Bp + (kt + 1) * 16;
            ra0 = *(const float4*)(Ap2);
            ra1 = *(const float4*)(Ap2 + a64);
            rb0 = *(const float4*)(Bp2);
            rb1 = *(const float4*)(Bp2 + b64);
        }
        compute_tile_nt(As[buf], Bs[buf], wm, wn, grp, tig, acc);
        if (pf) {
            const int nb = buf ^ 1;
            *(uint4*)&As[nb][r0     ][kq] = make_uint4(f2tf(ra0.x), f2tf(ra0.y), f2tf(ra0.z), f2tf(ra0.w));
            *(uint4*)&As[nb][r0 + 64][kq] = make_uint4(f2tf(ra1.x), f2tf(ra1.y), f2tf(ra1.z), f2tf(ra1.w));
            *(uint4*)&Bs[nb][r0     ][kq] = make_uint4(f2tf(rb0.x), f2tf(rb0.y), f2tf(rb0.z), f2tf(rb0.w));
            *(uint4*)&Bs[nb][r0 + 64][kq] = make_uint4(f2tf(rb1.x), f2tf(rb1.y), f2tf(rb1.z), f2tf(rb1.w));
        }
        __syncthreads();
    }
}

// ---------------------------------------------------------------------------
// NN mainloop: C(128x128 at (by,bx)) += A[M,K] * B[K,N], double buffered.
// ---------------------------------------------------------------------------
__device__ __forceinline__ void gemm_nn_main(
    const float* __restrict__ A, const float* __restrict__ B,
    int lda, int ldb, int ktiles, float acc[4][4][4])
{
    __shared__ unsigned As[2][128][20];
    __shared__ unsigned Bs[2][16][136];

    const int tid = threadIdx.x;
    const int r0  = tid >> 2;
    const int kq  = (tid & 3) << 2;
    const float* Ap = A + (size_t)(blockIdx.y * 128 + r0) * lda + kq;
    const size_t a64 = (size_t)64 * lda;

    const int bkr = tid >> 5;            // 0..7
    const int bnq = (tid & 31) << 2;     // 0..124
    const float* Bp = B + (size_t)bkr * ldb + blockIdx.x * 128 + bnq;
    const size_t b8 = (size_t)8 * ldb;

    float4 ra0 = *(const float4*)(Ap);
    float4 ra1 = *(const float4*)(Ap + a64);
    float4 rb0 = *(const float4*)(Bp);
    float4 rb1 = *(const float4*)(Bp + b8);
    *(uint4*)&As[0][r0     ][kq] = make_uint4(f2tf(ra0.x), f2tf(ra0.y), f2tf(ra0.z), f2tf(ra0.w));
    *(uint4*)&As[0][r0 + 64][kq] = make_uint4(f2tf(ra1.x), f2tf(ra1.y), f2tf(ra1.z), f2tf(ra1.w));
    *(uint4*)&Bs[0][bkr    ][bnq] = make_uint4(f2tf(rb0.x), f2tf(rb0.y), f2tf(rb0.z), f2tf(rb0.w));
    *(uint4*)&Bs[0][bkr + 8][bnq] = make_uint4(f2tf(rb1.x), f2tf(rb1.y), f2tf(rb1.z), f2tf(rb1.w));
    __syncthreads();

    const int lane = tid & 31;
    const int warp = tid >> 5;
    const int wm  = (warp >> 2) * 64;
    const int wn  = (warp & 3) * 32;
    const int grp = lane >> 2;
    const int tig = lane & 3;

#pragma unroll 1
    for (int kt = 0; kt < ktiles; kt++) {
        const int buf = kt & 1;
        const bool pf = (kt + 1 < ktiles);
        if (pf) {
            const float* Ap2 = Ap + (kt + 1) * 16;
            const float* Bp2 = Bp + (size_t)((kt + 1) * 16) * ldb;
            ra0 = *(const float4*)(Ap2);
            ra1 = *(const float4*)(Ap2 + a64);
            rb0 = *(const float4*)(Bp2);
            rb1 = *(const float4*)(Bp2 + b8);
        }
        compute_tile_nn(As[buf], Bs[buf], wm, wn, grp, tig, acc);
        if (pf) {
            const int nb = buf ^ 1;
            *(uint4*)&As[nb][r0     ][kq] = make_uint4(f2tf(ra0.x), f2tf(ra0.y), f2tf(ra0.z), f2tf(ra0.w));
            *(uint4*)&As[nb][r0 + 64][kq] = make_uint4(f2tf(ra1.x), f2tf(ra1.y), f2tf(ra1.z), f2tf(ra1.w));
            *(uint4*)&Bs[nb][bkr    ][bnq] = make_uint4(f2tf(rb0.x), f2tf(rb0.y), f2tf(rb0.z), f2tf(rb0.w));
            *(uint4*)&Bs[nb][bkr + 8][bnq] = make_uint4(f2tf(rb1.x), f2tf(rb1.y), f2tf(rb1.z), f2tf(rb1.w));
        }
        __syncthreads();
    }
}

// ---------------------------------------------------------------------------
// Kernel 1: QKV projections. y = x @ W^T + b. grid (4, 128, 3)
// ---------------------------------------------------------------------------
__global__ void __launch_bounds__(256, 2) proj_kernel(
    const float* __restrict__ X,
    const float* __restrict__ Wq, const float* __restrict__ bq,
    const float* __restrict__ Wk, const float* __restrict__ bk,
    const float* __restrict__ Wv, const float* __restrict__ bv)
{
    const float* W; const float* bias; float* C;
    if (blockIdx.z == 0)      { W = Wq; bias = bq; C = g_Q; }
    else if (blockIdx.z == 1) { W = Wk; bias = bk; C = g_K; }
    else                      { W = Wv; bias = bv; C = g_V; }

    float acc[4][4][4];
#pragma unroll
    for (int i = 0; i < 4; i++)
#pragma unroll
        for (int j = 0; j < 4; j++)
#pragma unroll
            for (int v = 0; v < 4; v++) acc[i][j][v] = 0.f;

    gemm_nt_main(X, W, DIM, DIM, DIM / 16, acc);

    const int lane = threadIdx.x & 31;
    const int warp = threadIdx.x >> 5;
    const int wm  = (warp >> 2) * 64;
    const int wn  = (warp & 3) * 32;
    const int grp = lane >> 2;
    const int tig = lane & 3;
#pragma unroll
    for (int i = 0; i < 4; i++) {
        const int row = blockIdx.y * 128 + wm + i * 16 + grp;
#pragma unroll
        for (int j = 0; j < 4; j++) {
            const int col = blockIdx.x * 128 + wn + j * 8 + 2 * tig;
            const float bv0 = bias[col], bv1 = bias[col + 1];
            *(float2*)&C[(size_t)row * DIM + col] =
                make_float2(acc[i][j][0] + bv0, acc[i][j][1] + bv1);
            *(float2*)&C[(size_t)(row + 8) * DIM + col] =
                make_float2(acc[i][j][2] + bv0, acc[i][j][3] + bv1);
        }
    }
}

// ---------------------------------------------------------------------------
// Kernel 2: scores = (Q K^T)/sqrt(D), masked. grid (16, 16, 8)
// ---------------------------------------------------------------------------
__global__ void __launch_bounds__(256, 2) scores_kernel(const int* __restrict__ mask)
{
    const int b = blockIdx.z;
    float acc[4][4][4];
#pragma unroll
    for (int i = 0; i < 4; i++)
#pragma unroll
        for (int j = 0; j < 4; j++)
#pragma unroll
            for (int v = 0; v < 4; v++) acc[i][j][v] = 0.f;

    gemm_nt_main(g_Q + (size_t)b * NSEQ * DIM, g_K + (size_t)b * NSEQ * DIM,
                 DIM, DIM, DIM / 16, acc);

    const float scale = 0.04419417382415922f;  // 1/sqrt(512)
    const int lane = threadIdx.x & 31;
    const int warp = threadIdx.x >> 5;
    const int wm  = (warp >> 2) * 64;
    const int wn  = (warp & 3) * 32;
    const int grp = lane >> 2;
    const int tig = lane & 3;
    const int* mrow = mask + (size_t)b * NSEQ;
    float* C = g_S + (size_t)b * NSEQ * NSEQ;
#pragma unroll
    for (int i = 0; i < 4; i++) {
        const int row = blockIdx.y * 128 + wm + i * 16 + grp;
#pragma unroll
        for (int j = 0; j < 4; j++) {
            const int col = blockIdx.x * 128 + wn + j * 8 + 2 * tig;
            const bool k0 = (mrow[col] == 0);
            const bool k1 = (mrow[col + 1] == 0);
            float v0 = k0 ? -1e9f : acc[i][j][0] * scale;
            float v1 = k1 ? -1e9f : acc[i][j][1] * scale;
            float v2 = k0 ? -1e9f : acc[i][j][2] * scale;
            float v3 = k1 ? -1e9f : acc[i][j][3] * scale;
            *(float2*)&C[(size_t)row * NSEQ + col]       = make_float2(v0, v1);
            *(float2*)&C[(size_t)(row + 8) * NSEQ + col] = make_float2(v2, v3);
        }
    }
}

// ---------------------------------------------------------------------------
// Kernel 3: in-place row softmax over 2048 elements. One block per row.
// ---------------------------------------------------------------------------
__global__ void __launch_bounds__(256) softmax_kernel()
{
    __shared__ float sred[8];
    float* r = g_S + (size_t)blockIdx.x * NSEQ;
    const int tid = threadIdx.x;

    float v[8];
    float m = -INFINITY;
#pragma unroll
    for (int t = 0; t < 8; t++) {
        v[t] = r[tid + t * 256];
        m = fmaxf(m, v[t]);
    }
#pragma unroll
    for (int off = 16; off > 0; off >>= 1)
        m = fmaxf(m, __shfl_xor_sync(0xffffffffu, m, off));
    if ((tid & 31) == 0) sred[tid >> 5] = m;
    __syncthreads();
    m = sred[0];
#pragma unroll
    for (int w = 1; w < 8; w++) m = fmaxf(m, sred[w]);

    float s = 0.f;
#pragma unroll
    for (int t = 0; t < 8; t++) {
        v[t] = __expf(v[t] - m);
        s += v[t];
    }
#pragma unroll
    for (int off = 16; off > 0; off >>= 1)
        s += __shfl_xor_sync(0xffffffffu, s, off);
    __syncthreads();
    if ((tid & 31) == 0) sred[tid >> 5] = s;
    __syncthreads();
    s = 0.f;
#pragma unroll
    for (int w = 0; w < 8; w++) s += sred[w];
    const float inv = 1.0f / s;
#pragma unroll
    for (int t = 0; t < 8; t++)
        r[tid + t * 256] = v[t] * inv;
}

// ---------------------------------------------------------------------------
// Kernel 4: O = P @ V. grid (4, 16, 8)
// ---------------------------------------------------------------------------
__global__ void __launch_bounds__(256, 2) av_kernel(float* __restrict__ out)
{
    const int b = blockIdx.z;
    float acc[4][4][4];
#pragma unroll
    for (int i = 0; i < 4; i++)
#pragma unroll
        for (int j = 0; j < 4; j++)
#pragma unroll
            for (int v = 0; v < 4; v++) acc[i][j][v] = 0.f;

    gemm_nn_main(g_S + (size_t)b * NSEQ * NSEQ, g_V + (size_t)b * NSEQ * DIM,
                 NSEQ, DIM, NSEQ / 16, acc);

    float* C = out + (size_t)b * NSEQ * DIM;
    const int lane = threadIdx.x & 31;
    const int warp = threadIdx.x >> 5;
    const int wm  = (warp >> 2) * 64;
    const int wn  = (warp & 3) * 32;
    const int grp = lane >> 2;
    const int tig = lane & 3;
#pragma unroll
    for (int i = 0; i < 4; i++) {
        const int row = blockIdx.y * 128 + wm + i * 16 + grp;
#pragma unroll
        for (int j = 0; j < 4; j++) {
            const int col = blockIdx.x * 128 + wn + j * 8 + 2 * tig;
            *(float2*)&C[(size_t)row * DIM + col] =
                make_float2(acc[i][j][0], acc[i][j][1]);
            *(float2*)&C[(size_t)(row + 8) * DIM + col] =
                make_float2(acc[i][j][2], acc[i][j][3]);
        }
    }
}

// ---------------------------------------------------------------------------
// Launch
// ---------------------------------------------------------------------------
extern "C" void kernel_launch(void* const* d_in, const int* in_sizes, int n_in,
                              void* d_out, int out_size)
{
    const float* X    = (const float*)d_in[0];
    const int*   mask = (const int*)  d_in[1];
    const float* Wk   = (const float*)d_in[2];
    const float* bk   = (const float*)d_in[3];
    const float* Wq   = (const float*)d_in[4];
    const float* bq   = (const float*)d_in[5];
    const float* Wv   = (const float*)d_in[6];
    const float* bv   = (const float*)d_in[7];
    float* out = (float*)d_out;

    proj_kernel  <<<dim3(DIM / 128, MTOT / 128, 3), 256>>>(X, Wq, bq, Wk, bk, Wv, bv);
    scores_kernel<<<dim3(NSEQ / 128, NSEQ / 128, BB), 256>>>(mask);
    softmax_kernel<<<MTOT, 256>>>();
    av_kernel    <<<dim3(DIM / 128, NSEQ / 128, BB), 256>>>(out);
}

// round 9
// speedup vs baseline: 5.2571x; 1.6810x over previous
#include <cuda_runtime.h>
#include <cuda_fp16.h>
#include <math.h>
#include <stdint.h>

#define BB 8
#define NSEQ 2048
#define DIM 512
#define MTOT (BB * NSEQ)

// Scratch (alloc-free rule: __device__ globals)
__device__ __half g_Qh[(size_t)MTOT * DIM];
__device__ __half g_Kh[(size_t)MTOT * DIM];
__device__ __half g_Vh[(size_t)MTOT * DIM];
__device__ __half g_Vth[(size_t)BB * DIM * NSEQ];   // [b][d][n]
__device__ float  g_S[(size_t)BB * NSEQ * NSEQ];    // fp32 logits
__device__ __half g_P[(size_t)BB * NSEQ * NSEQ];    // fp16 probabilities

// ---------------------------------------------------------------------------
// helpers
// ---------------------------------------------------------------------------
__device__ __forceinline__ unsigned pk(float a, float b) {
    __half2 h = __floats2half2_rn(a, b);
    return *reinterpret_cast<unsigned*>(&h);
}

// m16n8k16 fp16 MMA, fp32 accum. Word-level operand addressing is identical
// to the (proven) m16n8k8 tf32 scheme: a word = half2 = one k-pair.
__device__ __forceinline__ void mma16(float c[4],
                                      unsigned a0, unsigned a1, unsigned a2, unsigned a3,
                                      unsigned b0, unsigned b1) {
    asm volatile(
        "mma.sync.aligned.m16n8k16.row.col.f32.f16.f16.f32 "
        "{%0,%1,%2,%3}, {%4,%5,%6,%7}, {%8,%9}, {%0,%1,%2,%3};"
        : "+f"(c[0]), "+f"(c[1]), "+f"(c[2]), "+f"(c[3])
        : "r"(a0), "r"(a1), "r"(a2), "r"(a3), "r"(b0), "r"(b1));
}

// ---------------------------------------------------------------------------
// Fragment compute for one 128x128 x (32 halves) smem tile.
// As/Bs: [128][20] uint words (16 data words = 32 halves + 4 pad), K-major.
// Warp tile 64x32: 4 m-frags(16) x 4 n-frags(8), 2 k-steps of 16 halves.
// ---------------------------------------------------------------------------
__device__ __forceinline__ void compute_tile(
    const unsigned (*As)[20], const unsigned (*Bs)[20],
    int wm, int wn, int grp, int tig, float acc[4][4][4])
{
#pragma unroll
    for (int ks = 0; ks < 2; ks++) {
        unsigned af[4][4], bf[4][2];
        const int k = ks * 8 + tig;
#pragma unroll
        for (int i = 0; i < 4; i++) {
            const int r = wm + i * 16 + grp;
            af[i][0] = As[r][k];
            af[i][1] = As[r + 8][k];
            af[i][2] = As[r][k + 4];
            af[i][3] = As[r + 8][k + 4];
        }
#pragma unroll
        for (int j = 0; j < 4; j++) {
            const int c = wn + j * 8 + grp;
            bf[j][0] = Bs[c][k];
            bf[j][1] = Bs[c][k + 4];
        }
#pragma unroll
        for (int i = 0; i < 4; i++)
#pragma unroll
            for (int j = 0; j < 4; j++)
                mma16(acc[i][j], af[i][0], af[i][1], af[i][2], af[i][3],
                      bf[j][0], bf[j][1]);
    }
}

// ---------------------------------------------------------------------------
// NT mainloop, fp16 sources: C(128x128 at (by,bx)) += A[M,K] * B[N,K]^T.
// K_TILE = 32 halves. Double buffered, register-staged.
// ---------------------------------------------------------------------------
__device__ __forceinline__ void gemm_nt_h(
    const __half* __restrict__ A, const __half* __restrict__ B,
    int lda, int ldb, int ktiles, float acc[4][4][4])
{
    __shared__ unsigned As[2][128][20];
    __shared__ unsigned Bs[2][128][20];

    const int tid = threadIdx.x;
    const int r0  = tid >> 2;            // 0..63
    const int q   = tid & 3;
    const int wq  = q << 2;              // word col 0,4,8,12
    const __half* Ap = A + (size_t)(blockIdx.y * 128 + r0) * lda + (q << 3);
    const __half* Bp = B + (size_t)(blockIdx.x * 128 + r0) * ldb + (q << 3);
    const size_t a64 = (size_t)64 * lda;
    const size_t b64 = (size_t)64 * ldb;

    uint4 ra0 = *(const uint4*)(Ap);
    uint4 ra1 = *(const uint4*)(Ap + a64);
    uint4 rb0 = *(const uint4*)(Bp);
    uint4 rb1 = *(const uint4*)(Bp + b64);
    *(uint4*)&As[0][r0     ][wq] = ra0;
    *(uint4*)&As[0][r0 + 64][wq] = ra1;
    *(uint4*)&Bs[0][r0     ][wq] = rb0;
    *(uint4*)&Bs[0][r0 + 64][wq] = rb1;
    __syncthreads();

    const int lane = tid & 31;
    const int warp = tid >> 5;
    const int wm  = (warp >> 2) * 64;
    const int wn  = (warp & 3) * 32;
    const int grp = lane >> 2;
    const int tig = lane & 3;

#pragma unroll 1
    for (int kt = 0; kt < ktiles; kt++) {
        const int buf = kt & 1;
        const bool pf = (kt + 1 < ktiles);
        if (pf) {
            const __half* Ap2 = Ap + (kt + 1) * 32;
            const __half* Bp2 = Bp + (kt + 1) * 32;
            ra0 = *(const uint4*)(Ap2);
            ra1 = *(const uint4*)(Ap2 + a64);
            rb0 = *(const uint4*)(Bp2);
            rb1 = *(const uint4*)(Bp2 + b64);
        }
        compute_tile(As[buf], Bs[buf], wm, wn, grp, tig, acc);
        if (pf) {
            const int nb = buf ^ 1;
            *(uint4*)&As[nb][r0     ][wq] = ra0;
            *(uint4*)&As[nb][r0 + 64][wq] = ra1;
            *(uint4*)&Bs[nb][r0     ][wq] = rb0;
            *(uint4*)&Bs[nb][r0 + 64][wq] = rb1;
        }
        __syncthreads();
    }
}

// ---------------------------------------------------------------------------
// NT mainloop, fp32 sources converted to fp16 at fill (proj kernel).
// ---------------------------------------------------------------------------
__device__ __forceinline__ uint4 ld_cvt8(const float* p) {
    const float4 f0 = *(const float4*)(p);
    const float4 f1 = *(const float4*)(p + 4);
    return make_uint4(pk(f0.x, f0.y), pk(f0.z, f0.w), pk(f1.x, f1.y), pk(f1.z, f1.w));
}

__device__ __forceinline__ void gemm_nt_f(
    const float* __restrict__ A, const float* __restrict__ B,
    int lda, int ldb, int ktiles, float acc[4][4][4])
{
    __shared__ unsigned As[2][128][20];
    __shared__ unsigned Bs[2][128][20];

    const int tid = threadIdx.x;
    const int r0  = tid >> 2;
    const int q   = tid & 3;
    const int wq  = q << 2;
    const float* Ap = A + (size_t)(blockIdx.y * 128 + r0) * lda + (q << 3);
    const float* Bp = B + (size_t)(blockIdx.x * 128 + r0) * ldb + (q << 3);
    const size_t a64 = (size_t)64 * lda;
    const size_t b64 = (size_t)64 * ldb;

    uint4 ra0 = ld_cvt8(Ap);
    uint4 ra1 = ld_cvt8(Ap + a64);
    uint4 rb0 = ld_cvt8(Bp);
    uint4 rb1 = ld_cvt8(Bp + b64);
    *(uint4*)&As[0][r0     ][wq] = ra0;
    *(uint4*)&As[0][r0 + 64][wq] = ra1;
    *(uint4*)&Bs[0][r0     ][wq] = rb0;
    *(uint4*)&Bs[0][r0 + 64][wq] = rb1;
    __syncthreads();

    const int lane = tid & 31;
    const int warp = tid >> 5;
    const int wm  = (warp >> 2) * 64;
    const int wn  = (warp & 3) * 32;
    const int grp = lane >> 2;
    const int tig = lane & 3;

#pragma unroll 1
    for (int kt = 0; kt < ktiles; kt++) {
        const int buf = kt & 1;
        const bool pf = (kt + 1 < ktiles);
        if (pf) {
            const float* Ap2 = Ap + (kt + 1) * 32;
            const float* Bp2 = Bp + (kt + 1) * 32;
            ra0 = ld_cvt8(Ap2);
            ra1 = ld_cvt8(Ap2 + a64);
            rb0 = ld_cvt8(Bp2);
            rb1 = ld_cvt8(Bp2 + b64);
        }
        compute_tile(As[buf], Bs[buf], wm, wn, grp, tig, acc);
        if (pf) {
            const int nb = buf ^ 1;
            *(uint4*)&As[nb][r0     ][wq] = ra0;
            *(uint4*)&As[nb][r0 + 64][wq] = ra1;
            *(uint4*)&Bs[nb][r0     ][wq] = rb0;
            *(uint4*)&Bs[nb][r0 + 64][wq] = rb1;
        }
        __syncthreads();
    }
}

// ---------------------------------------------------------------------------
// Kernel 1: QKV projections. y = x @ W^T + b, output fp16. grid (4, 128, 3)
// ---------------------------------------------------------------------------
__global__ void __launch_bounds__(256, 2) proj_kernel(
    const float* __restrict__ X,
    const float* __restrict__ Wq, const float* __restrict__ bq,
    const float* __restrict__ Wk, const float* __restrict__ bk,
    const float* __restrict__ Wv, const float* __restrict__ bv)
{
    const float* W; const float* bias; __half* C;
    if (blockIdx.z == 0)      { W = Wq; bias = bq; C = g_Qh; }
    else if (blockIdx.z == 1) { W = Wk; bias = bk; C = g_Kh; }
    else                      { W = Wv; bias = bv; C = g_Vh; }

    float acc[4][4][4];
#pragma unroll
    for (int i = 0; i < 4; i++)
#pragma unroll
        for (int j = 0; j < 4; j++)
#pragma unroll
            for (int v = 0; v < 4; v++) acc[i][j][v] = 0.f;

    gemm_nt_f(X, W, DIM, DIM, DIM / 32, acc);

    const int lane = threadIdx.x & 31;
    const int warp = threadIdx.x >> 5;
    const int wm  = (warp >> 2) * 64;
    const int wn  = (warp & 3) * 32;
    const int grp = lane >> 2;
    const int tig = lane & 3;
#pragma unroll
    for (int i = 0; i < 4; i++) {
        const int row = blockIdx.y * 128 + wm + i * 16 + grp;
#pragma unroll
        for (int j = 0; j < 4; j++) {
            const int col = blockIdx.x * 128 + wn + j * 8 + 2 * tig;
            const float bv0 = bias[col], bv1 = bias[col + 1];
            *(unsigned*)&C[(size_t)row * DIM + col] =
                pk(acc[i][j][0] + bv0, acc[i][j][1] + bv1);
            *(unsigned*)&C[(size_t)(row + 8) * DIM + col] =
                pk(acc[i][j][2] + bv0, acc[i][j][3] + bv1);
        }
    }
}

// ---------------------------------------------------------------------------
// Kernel 2: transpose V -> Vt [b][d][n] (fp16). grid (16, 64, 8), block (32,8)
// ---------------------------------------------------------------------------
__global__ void __launch_bounds__(256) transpose_v()
{
    __shared__ __half t[32][33];
    const int b = blockIdx.z;
    const int d0 = blockIdx.x << 5, n0 = blockIdx.y << 5;
    const __half* src = g_Vh  + (size_t)b * NSEQ * DIM;
    __half*       dst = g_Vth + (size_t)b * DIM * NSEQ;
    const int tx = threadIdx.x, ty = threadIdx.y;
#pragma unroll
    for (int k = 0; k < 4; k++)
        t[ty + k * 8][tx] = src[(size_t)(n0 + ty + k * 8) * DIM + d0 + tx];
    __syncthreads();
#pragma unroll
    for (int k = 0; k < 4; k++)
        dst[(size_t)(d0 + ty + k * 8) * NSEQ + n0 + tx] = t[tx][ty + k * 8];
}

// ---------------------------------------------------------------------------
// Kernel 3: scores = mask(QK^T / sqrt(D)) -> fp32 S. grid (16, 16, 8)
// ---------------------------------------------------------------------------
__global__ void __launch_bounds__(256, 2) scores_kernel(const int* __restrict__ mask)
{
    const int b = blockIdx.z;
    float acc[4][4][4];
#pragma unroll
    for (int i = 0; i < 4; i++)
#pragma unroll
        for (int j = 0; j < 4; j++)
#pragma unroll
            for (int v = 0; v < 4; v++) acc[i][j][v] = 0.f;

    gemm_nt_h(g_Qh + (size_t)b * NSEQ * DIM, g_Kh + (size_t)b * NSEQ * DIM,
              DIM, DIM, DIM / 32, acc);

    const float scale = 0.04419417382415922f;  // 1/sqrt(512)
    const int lane = threadIdx.x & 31;
    const int warp = threadIdx.x >> 5;
    const int wm  = (warp >> 2) * 64;
    const int wn  = (warp & 3) * 32;
    const int grp = lane >> 2;
    const int tig = lane & 3;
    const int* mrow = mask + (size_t)b * NSEQ;
    float* C = g_S + (size_t)b * NSEQ * NSEQ;
#pragma unroll
    for (int i = 0; i < 4; i++) {
        const int row = blockIdx.y * 128 + wm + i * 16 + grp;
#pragma unroll
        for (int j = 0; j < 4; j++) {
            const int col = blockIdx.x * 128 + wn + j * 8 + 2 * tig;
            const bool k0 = (mrow[col] == 0);
            const bool k1 = (mrow[col + 1] == 0);
            float v0 = k0 ? -1e9f : acc[i][j][0] * scale;
            float v1 = k1 ? -1e9f : acc[i][j][1] * scale;
            float v2 = k0 ? -1e9f : acc[i][j][2] * scale;
            float v3 = k1 ? -1e9f : acc[i][j][3] * scale;
            *(float2*)&C[(size_t)row * NSEQ + col]       = make_float2(v0, v1);
            *(float2*)&C[(size_t)(row + 8) * NSEQ + col] = make_float2(v2, v3);
        }
    }
}

// ---------------------------------------------------------------------------
// Kernel 4: row softmax fp32 S -> fp16 P. One block (256 thr) per row.
// ---------------------------------------------------------------------------
__global__ void __launch_bounds__(256) softmax_kernel()
{
    __shared__ float sred[8];
    const float* r = g_S + (size_t)blockIdx.x * NSEQ;
    __half* o = g_P + (size_t)blockIdx.x * NSEQ;
    const int tid = threadIdx.x;

    float v[8];
    float m = -INFINITY;
#pragma unroll
    for (int t = 0; t < 8; t++) {
        v[t] = r[tid + t * 256];
        m = fmaxf(m, v[t]);
    }
#pragma unroll
    for (int off = 16; off > 0; off >>= 1)
        m = fmaxf(m, __shfl_xor_sync(0xffffffffu, m, off));
    if ((tid & 31) == 0) sred[tid >> 5] = m;
    __syncthreads();
    m = sred[0];
#pragma unroll
    for (int w = 1; w < 8; w++) m = fmaxf(m, sred[w]);

    float s = 0.f;
#pragma unroll
    for (int t = 0; t < 8; t++) {
        v[t] = __expf(v[t] - m);
        s += v[t];
    }
#pragma unroll
    for (int off = 16; off > 0; off >>= 1)
        s += __shfl_xor_sync(0xffffffffu, s, off);
    __syncthreads();
    if ((tid & 31) == 0) sred[tid >> 5] = s;
    __syncthreads();
    s = 0.f;
#pragma unroll
    for (int w = 0; w < 8; w++) s += sred[w];
    const float inv = 1.0f / s;
#pragma unroll
    for (int t = 0; t < 8; t++)
        o[tid + t * 256] = __float2half(v[t] * inv);
}

// ---------------------------------------------------------------------------
// Kernel 5: O = P @ Vt^T (NT, fp16 in / fp32 out). grid (4, 16, 8)
// ---------------------------------------------------------------------------
__global__ void __launch_bounds__(256, 2) av_kernel(float* __restrict__ out)
{
    const int b = blockIdx.z;
    float acc[4][4][4];
#pragma unroll
    for (int i = 0; i < 4; i++)
#pragma unroll
        for (int j = 0; j < 4; j++)
#pragma unroll
            for (int v = 0; v < 4; v++) acc[i][j][v] = 0.f;

    gemm_nt_h(g_P   + (size_t)b * NSEQ * NSEQ,
              g_Vth + (size_t)b * DIM * NSEQ,
              NSEQ, NSEQ, NSEQ / 32, acc);

    float* C = out + (size_t)b * NSEQ * DIM;
    const int lane = threadIdx.x & 31;
    const int warp = threadIdx.x >> 5;
    const int wm  = (warp >> 2) * 64;
    const int wn  = (warp & 3) * 32;
    const int grp = lane >> 2;
    const int tig = lane & 3;
#pragma unroll
    for (int i = 0; i < 4; i++) {
        const int row = blockIdx.y * 128 + wm + i * 16 + grp;
#pragma unroll
        for (int j = 0; j < 4; j++) {
            const int col = blockIdx.x * 128 + wn + j * 8 + 2 * tig;
            *(float2*)&C[(size_t)row * DIM + col] =
                make_float2(acc[i][j][0], acc[i][j][1]);
            *(float2*)&C[(size_t)(row + 8) * DIM + col] =
                make_float2(acc[i][j][2], acc[i][j][3]);
        }
    }
}

// ---------------------------------------------------------------------------
// Launch
// ---------------------------------------------------------------------------
extern "C" void kernel_launch(void* const* d_in, const int* in_sizes, int n_in,
                              void* d_out, int out_size)
{
    const float* X    = (const float*)d_in[0];
    const int*   mask = (const int*)  d_in[1];
    const float* Wk   = (const float*)d_in[2];
    const float* bk   = (const float*)d_in[3];
    const float* Wq   = (const float*)d_in[4];
    const float* bq   = (const float*)d_in[5];
    const float* Wv   = (const float*)d_in[6];
    const float* bv   = (const float*)d_in[7];
    float* out = (float*)d_out;

    proj_kernel  <<<dim3(DIM / 128, MTOT / 128, 3), 256>>>(X, Wq, bq, Wk, bk, Wv, bv);
    transpose_v  <<<dim3(DIM / 32, NSEQ / 32, BB), dim3(32, 8)>>>();
    scores_kernel<<<dim3(NSEQ / 128, NSEQ / 128, BB), 256>>>(mask);
    softmax_kernel<<<MTOT, 256>>>();
    av_kernel    <<<dim3(DIM / 128, NSEQ / 128, BB), 256>>>(out);
}

// round 11
// speedup vs baseline: 5.8193x; 1.1069x over previous
#include <cuda_runtime.h>
#include <cuda_fp16.h>
#include <math.h>
#include <stdint.h>

#define BB 8
#define NSEQ 2048
#define DIM 512
#define MTOT (BB * NSEQ)

// Scratch (alloc-free rule: __device__ globals)
__device__ __half g_Xh[(size_t)MTOT * DIM];
__device__ __half g_Wh[(size_t)3 * DIM * DIM];
__device__ __half g_Qh[(size_t)MTOT * DIM];
__device__ __half g_Kh[(size_t)MTOT * DIM];
__device__ __half g_Vh[(size_t)MTOT * DIM];
__device__ __half g_Vth[(size_t)BB * DIM * NSEQ];   // [b][d][n]
__device__ float  g_S[(size_t)BB * NSEQ * NSEQ];    // fp32 logits
__device__ __half g_P[(size_t)BB * NSEQ * NSEQ];    // fp16 probabilities

// ---------------------------------------------------------------------------
// helpers
// ---------------------------------------------------------------------------
__device__ __forceinline__ unsigned pk(float a, float b) {
    __half2 h = __floats2half2_rn(a, b);
    return *reinterpret_cast<unsigned*>(&h);
}
__device__ __forceinline__ uint32_t smem_u32(const void* p) {
    uint32_t a;
    asm("{ .reg .u64 t; cvta.to.shared.u64 t, %1; cvt.u32.u64 %0, t; }" : "=r"(a) : "l"(p));
    return a;
}
__device__ __forceinline__ void mma16(float c[4],
                                      unsigned a0, unsigned a1, unsigned a2, unsigned a3,
                                      unsigned b0, unsigned b1) {
    asm volatile(
        "mma.sync.aligned.m16n8k16.row.col.f32.f16.f16.f32 "
        "{%0,%1,%2,%3}, {%4,%5,%6,%7}, {%8,%9}, {%0,%1,%2,%3};"
        : "+f"(c[0]), "+f"(c[1]), "+f"(c[2]), "+f"(c[3])
        : "r"(a0), "r"(a1), "r"(a2), "r"(a3), "r"(b0), "r"(b1));
}
__device__ __forceinline__ void ldm_x4(unsigned& r0, unsigned& r1, unsigned& r2, unsigned& r3,
                                       uint32_t addr) {
    asm volatile("ldmatrix.sync.aligned.m8n8.x4.shared.b16 {%0,%1,%2,%3}, [%4];"
        : "=r"(r0), "=r"(r1), "=r"(r2), "=r"(r3) : "r"(addr));
}
__device__ __forceinline__ void cpa16(uint32_t dst, const void* src) {
    asm volatile("cp.async.ca.shared.global [%0], [%1], 16;" :: "r"(dst), "l"(src));
}
#define CP_COMMIT() asm volatile("cp.async.commit_group;" ::: "memory")
template<int N>
__device__ __forceinline__ void cp_wait() {
    asm volatile("cp.async.wait_group %0;" :: "n"(N) : "memory");
}

// ---------------------------------------------------------------------------
// GEMM NT: C(128x256 tile at (by,bx)) = A[M,K] * B[N,K]^T, fp16 in, fp32 acc.
// K-tile 32 halves. Smem row layout: stride 20 words (16 data + 4 pad, 80B):
// ldmatrix phases hit banks {0,20,8,28,16,4,24,12}(+c) -> conflict-free.
// A tile 128 rows at stage base, B tile 256 rows at +128*80.
// Warps 2(M) x 4(N), warp tile 64x64: 4 m-frags x 8 n-frags.
// ---------------------------------------------------------------------------
#define STAGE_BYTES (384 * 80)          // (128+256) rows * 80B
#define DYN_SMEM (2 * STAGE_BYTES)      // 61440

__device__ __forceinline__ void fill_stage(uint32_t sb,
                                           const __half* __restrict__ A,
                                           const __half* __restrict__ B,
                                           int lda, int ldb, int tid)
{
#pragma unroll
    for (int it = 0; it < 2; it++) {           // A: 128 rows x 4 chunks
        const int cid = it * 256 + tid;
        const int row = cid >> 2, c = cid & 3;
        cpa16(sb + row * 80 + c * 16, A + (size_t)row * lda + c * 8);
    }
#pragma unroll
    for (int it = 0; it < 4; it++) {           // B: 256 rows x 4 chunks
        const int cid = it * 256 + tid;
        const int row = cid >> 2, c = cid & 3;
        cpa16(sb + 128 * 80 + row * 80 + c * 16, B + (size_t)row * ldb + c * 8);
    }
}

__device__ __forceinline__ void gemm_nt_256(const __half* __restrict__ A,
                                            const __half* __restrict__ B,
                                            int lda, int ldb, int ktiles,
                                            float acc[4][8][4])
{
    extern __shared__ unsigned smdyn[];
    const uint32_t sb = smem_u32(smdyn);
    const int tid = threadIdx.x;

    A += (size_t)(blockIdx.y * 128) * lda;
    B += (size_t)(blockIdx.x * 256) * ldb;

    fill_stage(sb, A, B, lda, ldb, tid);
    CP_COMMIT();

    const int lane = tid & 31;
    const int warp = tid >> 5;
    const int wm = (warp & 1) * 64;
    const int wn = (warp >> 1) * 64;
    const uint32_t lro = (uint32_t)((lane & 15) * 80 + (lane >> 4) * 16);

#pragma unroll 1
    for (int kt = 0; kt < ktiles; kt++) {
        if (kt + 1 < ktiles) {
            fill_stage(sb + ((kt + 1) & 1) * STAGE_BYTES,
                       A + (kt + 1) * 32, B + (kt + 1) * 32, lda, ldb, tid);
            CP_COMMIT();
            cp_wait<1>();
        } else {
            cp_wait<0>();
        }
        __syncthreads();

        const uint32_t ab = sb + (kt & 1) * STAGE_BYTES;
        const uint32_t bb = ab + 128 * 80;
#pragma unroll
        for (int ks = 0; ks < 2; ks++) {
            unsigned af[4][4], bf[8][2];
#pragma unroll
            for (int i = 0; i < 4; i++)
                ldm_x4(af[i][0], af[i][1], af[i][2], af[i][3],
                       ab + (wm + i * 16) * 80 + ks * 32 + lro);
#pragma unroll
            for (int jj = 0; jj < 4; jj++)
                ldm_x4(bf[2 * jj][0], bf[2 * jj + 1][0], bf[2 * jj][1], bf[2 * jj + 1][1],
                       bb + (wn + jj * 16) * 80 + ks * 32 + lro);
#pragma unroll
            for (int i = 0; i < 4; i++)
#pragma unroll
                for (int j = 0; j < 8; j++)
                    mma16(acc[i][j], af[i][0], af[i][1], af[i][2], af[i][3],
                          bf[j][0], bf[j][1]);
        }
        __syncthreads();
    }
}

#define ACC_INIT(acc) \
    _Pragma("unroll") for (int i = 0; i < 4; i++) \
    _Pragma("unroll") for (int j = 0; j < 8; j++) \
    _Pragma("unroll") for (int v = 0; v < 4; v++) acc[i][j][v] = 0.f;

// ---------------------------------------------------------------------------
// Kernel 0: fp32 -> fp16 convert (grid-stride free, exact sizes from host)
// ---------------------------------------------------------------------------
__global__ void __launch_bounds__(256) cvt_kernel(const float* __restrict__ src,
                                                  __half* __restrict__ dst, int n4)
{
    const int i = blockIdx.x * 256 + threadIdx.x;
    if (i < n4) {
        const float4 f = ((const float4*)src)[i];
        ((uint2*)dst)[i] = make_uint2(pk(f.x, f.y), pk(f.z, f.w));
    }
}

// ---------------------------------------------------------------------------
// Kernel 1: QKV projections. grid (DIM/256=2, MTOT/128=128, 3)
// ---------------------------------------------------------------------------
__global__ void __launch_bounds__(256, 1) proj_tc(
    const float* __restrict__ bq, const float* __restrict__ bk,
    const float* __restrict__ bv)
{
    const float* bias; __half* C;
    if (blockIdx.z == 0)      { bias = bq; C = g_Qh; }
    else if (blockIdx.z == 1) { bias = bk; C = g_Kh; }
    else                      { bias = bv; C = g_Vh; }

    float acc[4][8][4];
    ACC_INIT(acc);
    gemm_nt_256(g_Xh, g_Wh + (size_t)blockIdx.z * DIM * DIM, DIM, DIM, DIM / 32, acc);

    const int lane = threadIdx.x & 31;
    const int warp = threadIdx.x >> 5;
    const int wm = (warp & 1) * 64;
    const int wn = (warp >> 1) * 64;
    const int grp = lane >> 2, tig = lane & 3;
#pragma unroll
    for (int i = 0; i < 4; i++) {
        const int row = blockIdx.y * 128 + wm + i * 16 + grp;
#pragma unroll
        for (int j = 0; j < 8; j++) {
            const int col = blockIdx.x * 256 + wn + j * 8 + 2 * tig;
            const float b0 = bias[col], b1 = bias[col + 1];
            *(unsigned*)&C[(size_t)row * DIM + col] =
                pk(acc[i][j][0] + b0, acc[i][j][1] + b1);
            *(unsigned*)&C[(size_t)(row + 8) * DIM + col] =
                pk(acc[i][j][2] + b0, acc[i][j][3] + b1);
        }
    }
}

// ---------------------------------------------------------------------------
// Kernel 2: transpose V -> Vt [b][d][n]. grid (16, 64, 8), block (32, 8)
// ---------------------------------------------------------------------------
__global__ void __launch_bounds__(256) transpose_v()
{
    __shared__ __half t[32][33];
    const int b = blockIdx.z;
    const int d0 = blockIdx.x << 5, n0 = blockIdx.y << 5;
    const __half* src = g_Vh  + (size_t)b * NSEQ * DIM;
    __half*       dst = g_Vth + (size_t)b * DIM * NSEQ;
    const int tx = threadIdx.x, ty = threadIdx.y;
#pragma unroll
    for (int k = 0; k < 4; k++)
        t[ty + k * 8][tx] = src[(size_t)(n0 + ty + k * 8) * DIM + d0 + tx];
    __syncthreads();
#pragma unroll
    for (int k = 0; k < 4; k++)
        dst[(size_t)(d0 + ty + k * 8) * NSEQ + n0 + tx] = t[tx][ty + k * 8];
}

// ---------------------------------------------------------------------------
// Kernel 3: scores = mask(QK^T / sqrt(D)) -> fp32 S. grid (8, 16, 8)
// ---------------------------------------------------------------------------
__global__ void __launch_bounds__(256, 1) scores_tc(const int* __restrict__ mask)
{
    const int b = blockIdx.z;
    float acc[4][8][4];
    ACC_INIT(acc);
    gemm_nt_256(g_Qh + (size_t)b * NSEQ * DIM, g_Kh + (size_t)b * NSEQ * DIM,
                DIM, DIM, DIM / 32, acc);

    const float scale = 0.04419417382415922f;  // 1/sqrt(512)
    const int lane = threadIdx.x & 31;
    const int warp = threadIdx.x >> 5;
    const int wm = (warp & 1) * 64;
    const int wn = (warp >> 1) * 64;
    const int grp = lane >> 2, tig = lane & 3;
    const int* mrow = mask + (size_t)b * NSEQ;
    float* C = g_S + (size_t)b * NSEQ * NSEQ;
#pragma unroll
    for (int i = 0; i < 4; i++) {
        const int row = blockIdx.y * 128 + wm + i * 16 + grp;
#pragma unroll
        for (int j = 0; j < 8; j++) {
            const int col = blockIdx.x * 256 + wn + j * 8 + 2 * tig;
            const bool k0 = (mrow[col] == 0);
            const bool k1 = (mrow[col + 1] == 0);
            const float v0 = k0 ? -1e9f : acc[i][j][0] * scale;
            const float v1 = k1 ? -1e9f : acc[i][j][1] * scale;
            const float v2 = k0 ? -1e9f : acc[i][j][2] * scale;
            const float v3 = k1 ? -1e9f : acc[i][j][3] * scale;
            *(float2*)&C[(size_t)row * NSEQ + col]       = make_float2(v0, v1);
            *(float2*)&C[(size_t)(row + 8) * NSEQ + col] = make_float2(v2, v3);
        }
    }
}

// ---------------------------------------------------------------------------
// Kernel 4: row softmax fp32 S -> fp16 P. One block (256 thr) per row.
// ---------------------------------------------------------------------------
__global__ void __launch_bounds__(256) softmax_kernel()
{
    __shared__ float sred[8];
    const float* r = g_S + (size_t)blockIdx.x * NSEQ;
    __half* o = g_P + (size_t)blockIdx.x * NSEQ;
    const int tid = threadIdx.x;

    float v[8];
    float m = -INFINITY;
#pragma unroll
    for (int t = 0; t < 8; t++) {
        v[t] = r[tid + t * 256];
        m = fmaxf(m, v[t]);
    }
#pragma unroll
    for (int off = 16; off > 0; off >>= 1)
        m = fmaxf(m, __shfl_xor_sync(0xffffffffu, m, off));
    if ((tid & 31) == 0) sred[tid >> 5] = m;
    __syncthreads();
    m = sred[0];
#pragma unroll
    for (int w = 1; w < 8; w++) m = fmaxf(m, sred[w]);

    float s = 0.f;
#pragma unroll
    for (int t = 0; t < 8; t++) {
        v[t] = __expf(v[t] - m);
        s += v[t];
    }
#pragma unroll
    for (int off = 16; off > 0; off >>= 1)
        s += __shfl_xor_sync(0xffffffffu, s, off);
    __syncthreads();
    if ((tid & 31) == 0) sred[tid >> 5] = s;
    __syncthreads();
    s = 0.f;
#pragma unroll
    for (int w = 0; w < 8; w++) s += sred[w];
    const float inv = 1.0f / s;
#pragma unroll
    for (int t = 0; t < 8; t++)
        o[tid + t * 256] = __float2half(v[t] * inv);
}

// ---------------------------------------------------------------------------
// Kernel 5: O = P @ Vt^T (NT). grid (DIM/256=2, 16, 8)
// ---------------------------------------------------------------------------
__global__ void __launch_bounds__(256, 1) av_tc(float* __restrict__ out)
{
    const int b = blockIdx.z;
    float acc[4][8][4];
    ACC_INIT(acc);
    gemm_nt_256(g_P   + (size_t)b * NSEQ * NSEQ,
                g_Vth + (size_t)b * DIM * NSEQ,
                NSEQ, NSEQ, NSEQ / 32, acc);

    float* C = out + (size_t)b * NSEQ * DIM;
    const int lane = threadIdx.x & 31;
    const int warp = threadIdx.x >> 5;
    const int wm = (warp & 1) * 64;
    const int wn = (warp >> 1) * 64;
    const int grp = lane >> 2, tig = lane & 3;
#pragma unroll
    for (int i = 0; i < 4; i++) {
        const int row = blockIdx.y * 128 + wm + i * 16 + grp;
#pragma unroll
        for (int j = 0; j < 8; j++) {
            const int col = blockIdx.x * 256 + wn + j * 8 + 2 * tig;
            *(float2*)&C[(size_t)row * DIM + col] =
                make_float2(acc[i][j][0], acc[i][j][1]);
            *(float2*)&C[(size_t)(row + 8) * DIM + col] =
                make_float2(acc[i][j][2], acc[i][j][3]);
        }
    }
}

// ---------------------------------------------------------------------------
// Launch
// ---------------------------------------------------------------------------
extern "C" void kernel_launch(void* const* d_in, const int* in_sizes, int n_in,
                              void* d_out, int out_size)
{
    const float* X    = (const float*)d_in[0];
    const int*   mask = (const int*)  d_in[1];
    const float* Wk   = (const float*)d_in[2];
    const float* bk   = (const float*)d_in[3];
    const float* Wq   = (const float*)d_in[4];
    const float* bq   = (const float*)d_in[5];
    const float* Wv   = (const float*)d_in[6];
    const float* bv   = (const float*)d_in[7];
    float* out = (float*)d_out;

    cudaFuncSetAttribute(proj_tc,   cudaFuncAttributeMaxDynamicSharedMemorySize, DYN_SMEM);
    cudaFuncSetAttribute(scores_tc, cudaFuncAttributeMaxDynamicSharedMemorySize, DYN_SMEM);
    cudaFuncSetAttribute(av_tc,     cudaFuncAttributeMaxDynamicSharedMemorySize, DYN_SMEM);

    __half* wq_h; __half* wk_h; __half* wv_h; __half* x_h;
    cudaGetSymbolAddress((void**)&x_h,  g_Xh);
    cudaGetSymbolAddress((void**)&wq_h, g_Wh);
    wk_h = wq_h + (size_t)DIM * DIM;
    wv_h = wq_h + (size_t)2 * DIM * DIM;

    const int nx4 = MTOT * DIM / 4;          // 2097152
    const int nw4 = DIM * DIM / 4;           // 65536
    cvt_kernel<<<(nx4 + 255) / 256, 256>>>(X,  x_h,  nx4);
    cvt_kernel<<<(nw4 + 255) / 256, 256>>>(Wq, wq_h, nw4);
    cvt_kernel<<<(nw4 + 255) / 256, 256>>>(Wk, wk_h, nw4);
    cvt_kernel<<<(nw4 + 255) / 256, 256>>>(Wv, wv_h, nw4);

    proj_tc   <<<dim3(DIM / 256, MTOT / 128, 3), 256, DYN_SMEM>>>(bq, bk, bv);
    transpose_v<<<dim3(DIM / 32, NSEQ / 32, BB), dim3(32, 8)>>>();
    scores_tc <<<dim3(NSEQ / 256, NSEQ / 128, BB), 256, DYN_SMEM>>>(mask);
    softmax_kernel<<<MTOT, 256>>>();
    av_tc     <<<dim3(DIM / 256, NSEQ / 128, BB), 256, DYN_SMEM>>>(out);
}

// round 13
// speedup vs baseline: 6.6088x; 1.1357x over previous
#include <cuda_runtime.h>
#include <cuda_fp16.h>
#include <math.h>
#include <stdint.h>

#define BB 8
#define NSEQ 2048
#define DIM 512
#define MTOT (BB * NSEQ)

// Scratch (alloc-free rule: __device__ globals)
__device__ __half g_Xh[(size_t)MTOT * DIM];
__device__ __half g_Wh[(size_t)3 * DIM * DIM];
__device__ __half g_Qh[(size_t)MTOT * DIM];
__device__ __half g_Kh[(size_t)MTOT * DIM];
__device__ __half g_Vh[(size_t)MTOT * DIM];
__device__ __half g_Vth[(size_t)BB * DIM * NSEQ];   // [b][d][n]
__device__ float  g_S[(size_t)BB * NSEQ * NSEQ];    // fp32 logits
__device__ __half g_P[(size_t)BB * NSEQ * NSEQ];    // fp16 probabilities

// ---------------------------------------------------------------------------
// helpers
// ---------------------------------------------------------------------------
__device__ __forceinline__ unsigned pk(float a, float b) {
    __half2 h = __floats2half2_rn(a, b);
    return *reinterpret_cast<unsigned*>(&h);
}
__device__ __forceinline__ uint32_t smem_u32(const void* p) {
    uint32_t a;
    asm("{ .reg .u64 t; cvta.to.shared.u64 t, %1; cvt.u32.u64 %0, t; }" : "=r"(a) : "l"(p));
    return a;
}
__device__ __forceinline__ void mma16(float c[4],
                                      unsigned a0, unsigned a1, unsigned a2, unsigned a3,
                                      unsigned b0, unsigned b1) {
    asm volatile(
        "mma.sync.aligned.m16n8k16.row.col.f32.f16.f16.f32 "
        "{%0,%1,%2,%3}, {%4,%5,%6,%7}, {%8,%9}, {%0,%1,%2,%3};"
        : "+f"(c[0]), "+f"(c[1]), "+f"(c[2]), "+f"(c[3])
        : "r"(a0), "r"(a1), "r"(a2), "r"(a3), "r"(b0), "r"(b1));
}
__device__ __forceinline__ void ldm_x4(unsigned& r0, unsigned& r1, unsigned& r2, unsigned& r3,
                                       uint32_t addr) {
    asm volatile("ldmatrix.sync.aligned.m8n8.x4.shared.b16 {%0,%1,%2,%3}, [%4];"
        : "=r"(r0), "=r"(r1), "=r"(r2), "=r"(r3) : "r"(addr));
}
__device__ __forceinline__ void cpa16(uint32_t dst, const void* src) {
    asm volatile("cp.async.ca.shared.global [%0], [%1], 16;" :: "r"(dst), "l"(src));
}
#define CP_COMMIT() asm volatile("cp.async.commit_group;" ::: "memory")
template<int N>
__device__ __forceinline__ void cp_wait() {
    asm volatile("cp.async.wait_group %0;" :: "n"(N) : "memory");
}

// ---------------------------------------------------------------------------
// GEMM NT: C(128x256 tile at (by,bx)) = A[M,K] * B[N,K]^T, fp16 in, fp32 acc.
// K_TILE = 64 halves -> 128B data rows padded to 144B (36 words):
//   ldmatrix: 8 rows at 36r%32 words = {0,4,8,...,28} -> conflict-free.
//   cp.async: 8-lane phase = one full 128B row -> all 32 banks -> conflict-free.
// A tile: 128 rows at stage base; B tile: 256 rows at +128*144.
// 3-stage cp.async pipeline. Warps 2(M) x 4(N), warp tile 64x64.
// ---------------------------------------------------------------------------
#define KT 64
#define ROWB 144
#define STAGE_BYTES (384 * ROWB)            // 55296
#define NSTAGE 3
#define DYN_SMEM (NSTAGE * STAGE_BYTES)     // 165888

__device__ __forceinline__ void fill_stage(uint32_t sb,
                                           const __half* __restrict__ A,
                                           const __half* __restrict__ B,
                                           int lda, int ldb, int tid)
{
#pragma unroll
    for (int it = 0; it < 4; it++) {           // A: 128 rows x 8 chunks
        const int cid = it * 256 + tid;
        const int row = cid >> 3, c = cid & 7;
        cpa16(sb + row * ROWB + c * 16, A + (size_t)row * lda + c * 8);
    }
#pragma unroll
    for (int it = 0; it < 8; it++) {           // B: 256 rows x 8 chunks
        const int cid = it * 256 + tid;
        const int row = cid >> 3, c = cid & 7;
        cpa16(sb + 128 * ROWB + row * ROWB + c * 16, B + (size_t)row * ldb + c * 8);
    }
}

__device__ __forceinline__ void gemm_nt_256(const __half* __restrict__ A,
                                            const __half* __restrict__ B,
                                            int lda, int ldb, int ktiles,
                                            float acc[4][8][4])
{
    extern __shared__ unsigned smdyn[];
    const uint32_t sb = smem_u32(smdyn);
    const int tid = threadIdx.x;

    A += (size_t)(blockIdx.y * 128) * lda;
    B += (size_t)(blockIdx.x * 256) * ldb;

    fill_stage(sb, A, B, lda, ldb, tid);
    CP_COMMIT();
    if (ktiles > 1) {
        fill_stage(sb + STAGE_BYTES, A + KT, B + KT, lda, ldb, tid);
        CP_COMMIT();
    }

    const int lane = tid & 31;
    const int warp = tid >> 5;
    const int wm = (warp & 1) * 64;
    const int wn = (warp >> 1) * 64;
    const uint32_t lro = (uint32_t)((lane & 15) * ROWB + (lane >> 4) * 16);

#pragma unroll 1
    for (int kt = 0; kt < ktiles; kt++) {
        // __syncthreads of previous iteration guarantees stage (kt+2)%3 is free
        if (kt + 2 < ktiles) {
            fill_stage(sb + ((kt + 2) % NSTAGE) * STAGE_BYTES,
                       A + (size_t)(kt + 2) * KT, B + (size_t)(kt + 2) * KT,
                       lda, ldb, tid);
            CP_COMMIT();
            cp_wait<2>();
        } else if (kt + 1 < ktiles) {
            cp_wait<1>();
        } else {
            cp_wait<0>();
        }
        __syncthreads();          // stage kt visible to all warps

        const uint32_t ab = sb + (kt % NSTAGE) * STAGE_BYTES;
        const uint32_t bb = ab + 128 * ROWB;
#pragma unroll
        for (int ks = 0; ks < 4; ks++) {
            unsigned af[4][4], bf[8][2];
#pragma unroll
            for (int i = 0; i < 4; i++)
                ldm_x4(af[i][0], af[i][1], af[i][2], af[i][3],
                       ab + (wm + i * 16) * ROWB + ks * 32 + lro);
#pragma unroll
            for (int jj = 0; jj < 4; jj++)
                ldm_x4(bf[2 * jj][0], bf[2 * jj + 1][0], bf[2 * jj][1], bf[2 * jj + 1][1],
                       bb + (wn + jj * 16) * ROWB + ks * 32 + lro);
#pragma unroll
            for (int i = 0; i < 4; i++)
#pragma unroll
                for (int j = 0; j < 8; j++)
                    mma16(acc[i][j], af[i][0], af[i][1], af[i][2], af[i][3],
                          bf[j][0], bf[j][1]);
        }
        __syncthreads();          // all warps done reading stage kt (WAR for refill)
    }
}

#define ACC_INIT(acc) \
    _Pragma("unroll") for (int i = 0; i < 4; i++) \
    _Pragma("unroll") for (int j = 0; j < 8; j++) \
    _Pragma("unroll") for (int v = 0; v < 4; v++) acc[i][j][v] = 0.f;

// ---------------------------------------------------------------------------
// Kernel 0: fp32 -> fp16 convert
// ---------------------------------------------------------------------------
__global__ void __launch_bounds__(256) cvt_kernel(const float* __restrict__ src,
                                                  __half* __restrict__ dst, int n4)
{
    const int i = blockIdx.x * 256 + threadIdx.x;
    if (i < n4) {
        const float4 f = ((const float4*)src)[i];
        ((uint2*)dst)[i] = make_uint2(pk(f.x, f.y), pk(f.z, f.w));
    }
}

// ---------------------------------------------------------------------------
// Kernel 1: QKV projections. grid (DIM/256=2, MTOT/128=128, 3)
// ---------------------------------------------------------------------------
__global__ void __launch_bounds__(256, 1) proj_tc(
    const float* __restrict__ bq, const float* __restrict__ bk,
    const float* __restrict__ bv)
{
    const float* bias; __half* C;
    if (blockIdx.z == 0)      { bias = bq; C = g_Qh; }
    else if (blockIdx.z == 1) { bias = bk; C = g_Kh; }
    else                      { bias = bv; C = g_Vh; }

    float acc[4][8][4];
    ACC_INIT(acc);
    gemm_nt_256(g_Xh, g_Wh + (size_t)blockIdx.z * DIM * DIM, DIM, DIM, DIM / KT, acc);

    const int lane = threadIdx.x & 31;
    const int warp = threadIdx.x >> 5;
    const int wm = (warp & 1) * 64;
    const int wn = (warp >> 1) * 64;
    const int grp = lane >> 2, tig = lane & 3;
#pragma unroll
    for (int i = 0; i < 4; i++) {
        const int row = blockIdx.y * 128 + wm + i * 16 + grp;
#pragma unroll
        for (int j = 0; j < 8; j++) {
            const int col = blockIdx.x * 256 + wn + j * 8 + 2 * tig;
            const float b0 = bias[col], b1 = bias[col + 1];
            *(unsigned*)&C[(size_t)row * DIM + col] =
                pk(acc[i][j][0] + b0, acc[i][j][1] + b1);
            *(unsigned*)&C[(size_t)(row + 8) * DIM + col] =
                pk(acc[i][j][2] + b0, acc[i][j][3] + b1);
        }
    }
}

// ---------------------------------------------------------------------------
// Kernel 2: transpose V -> Vt [b][d][n]. grid (16, 64, 8), block (32, 8)
// ---------------------------------------------------------------------------
__global__ void __launch_bounds__(256) transpose_v()
{
    __shared__ __half t[32][33];
    const int b = blockIdx.z;
    const int d0 = blockIdx.x << 5, n0 = blockIdx.y << 5;
    const __half* src = g_Vh  + (size_t)b * NSEQ * DIM;
    __half*       dst = g_Vth + (size_t)b * DIM * NSEQ;
    const int tx = threadIdx.x, ty = threadIdx.y;
#pragma unroll
    for (int k = 0; k < 4; k++)
        t[ty + k * 8][tx] = src[(size_t)(n0 + ty + k * 8) * DIM + d0 + tx];
    __syncthreads();
#pragma unroll
    for (int k = 0; k < 4; k++)
        dst[(size_t)(d0 + ty + k * 8) * NSEQ + n0 + tx] = t[tx][ty + k * 8];
}

// ---------------------------------------------------------------------------
// Kernel 3: scores = mask(QK^T / sqrt(D)) -> fp32 S. grid (8, 16, 8)
// ---------------------------------------------------------------------------
__global__ void __launch_bounds__(256, 1) scores_tc(const int* __restrict__ mask)
{
    const int b = blockIdx.z;
    float acc[4][8][4];
    ACC_INIT(acc);
    gemm_nt_256(g_Qh + (size_t)b * NSEQ * DIM, g_Kh + (size_t)b * NSEQ * DIM,
                DIM, DIM, DIM / KT, acc);

    const float scale = 0.04419417382415922f;  // 1/sqrt(512)
    const int lane = threadIdx.x & 31;
    const int warp = threadIdx.x >> 5;
    const int wm = (warp & 1) * 64;
    const int wn = (warp >> 1) * 64;
    const int grp = lane >> 2, tig = lane & 3;
    const int* mrow = mask + (size_t)b * NSEQ;
    float* C = g_S + (size_t)b * NSEQ * NSEQ;
#pragma unroll
    for (int i = 0; i < 4; i++) {
        const int row = blockIdx.y * 128 + wm + i * 16 + grp;
#pragma unroll
        for (int j = 0; j < 8; j++) {
            const int col = blockIdx.x * 256 + wn + j * 8 + 2 * tig;
            const bool k0 = (mrow[col] == 0);
            const bool k1 = (mrow[col + 1] == 0);
            const float v0 = k0 ? -1e9f : acc[i][j][0] * scale;
            const float v1 = k1 ? -1e9f : acc[i][j][1] * scale;
            const float v2 = k0 ? -1e9f : acc[i][j][2] * scale;
            const float v3 = k1 ? -1e9f : acc[i][j][3] * scale;
            *(float2*)&C[(size_t)row * NSEQ + col]       = make_float2(v0, v1);
            *(float2*)&C[(size_t)(row + 8) * NSEQ + col] = make_float2(v2, v3);
        }
    }
}

// ---------------------------------------------------------------------------
// Kernel 4: row softmax fp32 S -> fp16 P. One block (256 thr) per row.
// ---------------------------------------------------------------------------
__global__ void __launch_bounds__(256) softmax_kernel()
{
    __shared__ float sred[8];
    const float* r = g_S + (size_t)blockIdx.x * NSEQ;
    __half* o = g_P + (size_t)blockIdx.x * NSEQ;
    const int tid = threadIdx.x;

    float v[8];
    float m = -INFINITY;
#pragma unroll
    for (int t = 0; t < 8; t++) {
        v[t] = r[tid + t * 256];
        m = fmaxf(m, v[t]);
    }
#pragma unroll
    for (int off = 16; off > 0; off >>= 1)
        m = fmaxf(m, __shfl_xor_sync(0xffffffffu, m, off));
    if ((tid & 31) == 0) sred[tid >> 5] = m;
    __syncthreads();
    m = sred[0];
#pragma unroll
    for (int w = 1; w < 8; w++) m = fmaxf(m, sred[w]);

    float s = 0.f;
#pragma unroll
    for (int t = 0; t < 8; t++) {
        v[t] = __expf(v[t] - m);
        s += v[t];
    }
#pragma unroll
    for (int off = 16; off > 0; off >>= 1)
        s += __shfl_xor_sync(0xffffffffu, s, off);
    __syncthreads();
    if ((tid & 31) == 0) sred[tid >> 5] = s;
    __syncthreads();
    s = 0.f;
#pragma unroll
    for (int w = 0; w < 8; w++) s += sred[w];
    const float inv = 1.0f / s;
#pragma unroll
    for (int t = 0; t < 8; t++)
        o[tid + t * 256] = __float2half(v[t] * inv);
}

// ---------------------------------------------------------------------------
// Kernel 5: O = P @ Vt^T (NT). grid (DIM/256=2, 16, 8)
// ---------------------------------------------------------------------------
__global__ void __launch_bounds__(256, 1) av_tc(float* __restrict__ out)
{
    const int b = blockIdx.z;
    float acc[4][8][4];
    ACC_INIT(acc);
    gemm_nt_256(g_P   + (size_t)b * NSEQ * NSEQ,
                g_Vth + (size_t)b * DIM * NSEQ,
                NSEQ, NSEQ, NSEQ / KT, acc);

    float* C = out + (size_t)b * NSEQ * DIM;
    const int lane = threadIdx.x & 31;
    const int warp = threadIdx.x >> 5;
    const int wm = (warp & 1) * 64;
    const int wn = (warp >> 1) * 64;
    const int grp = lane >> 2, tig = lane & 3;
#pragma unroll
    for (int i = 0; i < 4; i++) {
        const int row = blockIdx.y * 128 + wm + i * 16 + grp;
#pragma unroll
        for (int j = 0; j < 8; j++) {
            const int col = blockIdx.x * 256 + wn + j * 8 + 2 * tig;
            *(float2*)&C[(size_t)row * DIM + col] =
                make_float2(acc[i][j][0], acc[i][j][1]);
            *(float2*)&C[(size_t)(row + 8) * DIM + col] =
                make_float2(acc[i][j][2], acc[i][j][3]);
        }
    }
}

// ---------------------------------------------------------------------------
// Launch
// ---------------------------------------------------------------------------
extern "C" void kernel_launch(void* const* d_in, const int* in_sizes, int n_in,
                              void* d_out, int out_size)
{
    const float* X    = (const float*)d_in[0];
    const int*   mask = (const int*)  d_in[1];
    const float* Wk   = (const float*)d_in[2];
    const float* bk   = (const float*)d_in[3];
    const float* Wq   = (const float*)d_in[4];
    const float* bq   = (const float*)d_in[5];
    const float* Wv   = (const float*)d_in[6];
    const float* bv   = (const float*)d_in[7];
    float* out = (float*)d_out;

    cudaFuncSetAttribute(proj_tc,   cudaFuncAttributeMaxDynamicSharedMemorySize, DYN_SMEM);
    cudaFuncSetAttribute(scores_tc, cudaFuncAttributeMaxDynamicSharedMemorySize, DYN_SMEM);
    cudaFuncSetAttribute(av_tc,     cudaFuncAttributeMaxDynamicSharedMemorySize, DYN_SMEM);

    __half* wq_h; __half* x_h;
    cudaGetSymbolAddress((void**)&x_h,  g_Xh);
    cudaGetSymbolAddress((void**)&wq_h, g_Wh);
    __half* wk_h = wq_h + (size_t)DIM * DIM;
    __half* wv_h = wq_h + (size_t)2 * DIM * DIM;

    const int nx4 = MTOT * DIM / 4;
    const int nw4 = DIM * DIM / 4;
    cvt_kernel<<<(nx4 + 255) / 256, 256>>>(X,  x_h,  nx4);
    cvt_kernel<<<(nw4 + 255) / 256, 256>>>(Wq, wq_h, nw4);
    cvt_kernel<<<(nw4 + 255) / 256, 256>>>(Wk, wk_h, nw4);
    cvt_kernel<<<(nw4 + 255) / 256, 256>>>(Wv, wv_h, nw4);

    proj_tc   <<<dim3(DIM / 256, MTOT / 128, 3), 256, DYN_SMEM>>>(bq, bk, bv);
    transpose_v<<<dim3(DIM / 32, NSEQ / 32, BB), dim3(32, 8)>>>();
    scores_tc <<<dim3(NSEQ / 256, NSEQ / 128, BB), 256, DYN_SMEM>>>(mask);
    softmax_kernel<<<MTOT, 256>>>();
    av_tc     <<<dim3(DIM / 256, NSEQ / 128, BB), 256, DYN_SMEM>>>(out);
}

// round 15
// speedup vs baseline: 6.7773x; 1.0255x over previous
#include <cuda_runtime.h>
#include <cuda_fp16.h>
#include <math.h>
#include <stdint.h>

#define BB 8
#define NSEQ 2048
#define DIM 512
#define MTOT (BB * NSEQ)

// Scratch (alloc-free rule: __device__ globals)
__device__ __half g_Xh[(size_t)MTOT * DIM];
__device__ __half g_Wh[(size_t)3 * DIM * DIM];
__device__ __half g_Qh[(size_t)MTOT * DIM];
__device__ __half g_Kh[(size_t)MTOT * DIM];
__device__ __half g_Vth[(size_t)BB * DIM * NSEQ];   // [b][d][n]
__device__ float  g_S[(size_t)BB * NSEQ * NSEQ];    // fp32 logits
__device__ __half g_P[(size_t)BB * NSEQ * NSEQ];    // fp16 probabilities

// ---------------------------------------------------------------------------
// helpers
// ---------------------------------------------------------------------------
__device__ __forceinline__ unsigned pk(float a, float b) {
    __half2 h = __floats2half2_rn(a, b);
    return *reinterpret_cast<unsigned*>(&h);
}
__device__ __forceinline__ uint32_t smem_u32(const void* p) {
    uint32_t a;
    asm("{ .reg .u64 t; cvta.to.shared.u64 t, %1; cvt.u32.u64 %0, t; }" : "=r"(a) : "l"(p));
    return a;
}
__device__ __forceinline__ void mma16(float c[4],
                                      unsigned a0, unsigned a1, unsigned a2, unsigned a3,
                                      unsigned b0, unsigned b1) {
    asm volatile(
        "mma.sync.aligned.m16n8k16.row.col.f32.f16.f16.f32 "
        "{%0,%1,%2,%3}, {%4,%5,%6,%7}, {%8,%9}, {%0,%1,%2,%3};"
        : "+f"(c[0]), "+f"(c[1]), "+f"(c[2]), "+f"(c[3])
        : "r"(a0), "r"(a1), "r"(a2), "r"(a3), "r"(b0), "r"(b1));
}
__device__ __forceinline__ void ldm_x4(unsigned& r0, unsigned& r1, unsigned& r2, unsigned& r3,
                                       uint32_t addr) {
    asm volatile("ldmatrix.sync.aligned.m8n8.x4.shared.b16 {%0,%1,%2,%3}, [%4];"
        : "=r"(r0), "=r"(r1), "=r"(r2), "=r"(r3) : "r"(addr));
}
__device__ __forceinline__ void cpa16(uint32_t dst, const void* src) {
    asm volatile("cp.async.ca.shared.global [%0], [%1], 16;" :: "r"(dst), "l"(src));
}
#define CP_COMMIT() asm volatile("cp.async.commit_group;" ::: "memory")
template<int N>
__device__ __forceinline__ void cp_wait() {
    asm volatile("cp.async.wait_group %0;" :: "n"(N) : "memory");
}

// ---------------------------------------------------------------------------
// GEMM NT: C(128x256 tile at (by,bx)) = A[M,K] * B[N,K]^T, fp16 in, fp32 acc.
// K_TILE = 64 halves -> 128B data rows padded to 144B (36 words).
// 3-stage cp.async pipeline. Warps 2(M) x 4(N), warp tile 64x64.  [R13-proven]
// ---------------------------------------------------------------------------
#define KT 64
#define ROWB 144
#define STAGE_BYTES (384 * ROWB)            // 55296
#define NSTAGE 3
#define DYN_SMEM (NSTAGE * STAGE_BYTES)     // 165888

__device__ __forceinline__ void fill_stage(uint32_t sb,
                                           const __half* __restrict__ A,
                                           const __half* __restrict__ B,
                                           int lda, int ldb, int tid)
{
#pragma unroll
    for (int it = 0; it < 4; it++) {           // A: 128 rows x 8 chunks
        const int cid = it * 256 + tid;
        const int row = cid >> 3, c = cid & 7;
        cpa16(sb + row * ROWB + c * 16, A + (size_t)row * lda + c * 8);
    }
#pragma unroll
    for (int it = 0; it < 8; it++) {           // B: 256 rows x 8 chunks
        const int cid = it * 256 + tid;
        const int row = cid >> 3, c = cid & 7;
        cpa16(sb + 128 * ROWB + row * ROWB + c * 16, B + (size_t)row * ldb + c * 8);
    }
}

__device__ __forceinline__ void gemm_nt_256(const __half* __restrict__ A,
                                            const __half* __restrict__ B,
                                            int lda, int ldb, int ktiles,
                                            float acc[4][8][4])
{
    extern __shared__ unsigned smdyn[];
    const uint32_t sb = smem_u32(smdyn);
    const int tid = threadIdx.x;

    A += (size_t)(blockIdx.y * 128) * lda;
    B += (size_t)(blockIdx.x * 256) * ldb;

    fill_stage(sb, A, B, lda, ldb, tid);
    CP_COMMIT();
    if (ktiles > 1) {
        fill_stage(sb + STAGE_BYTES, A + KT, B + KT, lda, ldb, tid);
        CP_COMMIT();
    }

    const int lane = tid & 31;
    const int warp = tid >> 5;
    const int wm = (warp & 1) * 64;
    const int wn = (warp >> 1) * 64;
    const uint32_t lro = (uint32_t)((lane & 15) * ROWB + (lane >> 4) * 16);

#pragma unroll 1
    for (int kt = 0; kt < ktiles; kt++) {
        if (kt + 2 < ktiles) {
            fill_stage(sb + ((kt + 2) % NSTAGE) * STAGE_BYTES,
                       A + (size_t)(kt + 2) * KT, B + (size_t)(kt + 2) * KT,
                       lda, ldb, tid);
            CP_COMMIT();
            cp_wait<2>();
        } else if (kt + 1 < ktiles) {
            cp_wait<1>();
        } else {
            cp_wait<0>();
        }
        __syncthreads();

        const uint32_t ab = sb + (kt % NSTAGE) * STAGE_BYTES;
        const uint32_t bb = ab + 128 * ROWB;
#pragma unroll
        for (int ks = 0; ks < 4; ks++) {
            unsigned af[4][4], bf[8][2];
#pragma unroll
            for (int i = 0; i < 4; i++)
                ldm_x4(af[i][0], af[i][1], af[i][2], af[i][3],
                       ab + (wm + i * 16) * ROWB + ks * 32 + lro);
#pragma unroll
            for (int jj = 0; jj < 4; jj++)
                ldm_x4(bf[2 * jj][0], bf[2 * jj + 1][0], bf[2 * jj][1], bf[2 * jj + 1][1],
                       bb + (wn + jj * 16) * ROWB + ks * 32 + lro);
#pragma unroll
            for (int i = 0; i < 4; i++)
#pragma unroll
                for (int j = 0; j < 8; j++)
                    mma16(acc[i][j], af[i][0], af[i][1], af[i][2], af[i][3],
                          bf[j][0], bf[j][1]);
        }
        __syncthreads();
    }
}

#define ACC_INIT(acc) \
    _Pragma("unroll") for (int i = 0; i < 4; i++) \
    _Pragma("unroll") for (int j = 0; j < 8; j++) \
    _Pragma("unroll") for (int v = 0; v < 4; v++) acc[i][j][v] = 0.f;

// ---------------------------------------------------------------------------
// Kernel 0a: fp32 -> fp16 convert (X)
// ---------------------------------------------------------------------------
__global__ void __launch_bounds__(256) cvt_kernel(const float* __restrict__ src,
                                                  __half* __restrict__ dst, int n4)
{
    const int i = blockIdx.x * 256 + threadIdx.x;
    if (i < n4) {
        const float4 f = ((const float4*)src)[i];
        ((uint2*)dst)[i] = make_uint2(pk(f.x, f.y), pk(f.z, f.w));
    }
}

// Kernel 0b: convert 3 weight matrices in one launch. grid (256, 3)
__global__ void __launch_bounds__(256) cvtw_kernel(const float* __restrict__ wq,
                                                   const float* __restrict__ wk,
                                                   const float* __restrict__ wv)
{
    const float* src = (blockIdx.y == 0) ? wq : (blockIdx.y == 1) ? wk : wv;
    __half* dst = g_Wh + (size_t)blockIdx.y * DIM * DIM;
    const int i = blockIdx.x * 256 + threadIdx.x;   // n4 = 65536 exactly
    const float4 f = ((const float4*)src)[i];
    ((uint2*)dst)[i] = make_uint2(pk(f.x, f.y), pk(f.z, f.w));
}

// ---------------------------------------------------------------------------
// Kernel 1: QKV projections. grid (DIM/256=2, MTOT/128=128, 3)
// z==2 (V): result is staged in smem and written TRANSPOSED to g_Vth only.
// ---------------------------------------------------------------------------
__global__ void __launch_bounds__(256, 1) proj_tc(
    const float* __restrict__ bq, const float* __restrict__ bk,
    const float* __restrict__ bv)
{
    const float* bias = (blockIdx.z == 0) ? bq : (blockIdx.z == 1) ? bk : bv;

    float acc[4][8][4];
    ACC_INIT(acc);
    gemm_nt_256(g_Xh, g_Wh + (size_t)blockIdx.z * DIM * DIM, DIM, DIM, DIM / KT, acc);

    const int tid  = threadIdx.x;
    const int lane = tid & 31;
    const int warp = tid >> 5;
    const int wm = (warp & 1) * 64;
    const int wn = (warp >> 1) * 64;
    const int grp = lane >> 2, tig = lane & 3;

    if (blockIdx.z < 2) {
        __half* C = (blockIdx.z == 0) ? g_Qh : g_Kh;
#pragma unroll
        for (int i = 0; i < 4; i++) {
            const int row = blockIdx.y * 128 + wm + i * 16 + grp;
#pragma unroll
            for (int j = 0; j < 8; j++) {
                const int col = blockIdx.x * 256 + wn + j * 8 + 2 * tig;
                const float b0 = bias[col], b1 = bias[col + 1];
                *(unsigned*)&C[(size_t)row * DIM + col] =
                    pk(acc[i][j][0] + b0, acc[i][j][1] + b1);
                *(unsigned*)&C[(size_t)(row + 8) * DIM + col] =
                    pk(acc[i][j][2] + b0, acc[i][j][3] + b1);
            }
        }
    } else {
        // V: transpose through smem (reuse GEMM stages; mainloop ended with sync)
        extern __shared__ unsigned smdyn[];
        __half* Ts = reinterpret_cast<__half*>(smdyn);   // [256 d][136 n-stride]
        const int b  = blockIdx.y / 16;                  // batch (16 y-blocks per batch)
        const int n0 = (blockIdx.y % 16) * 128;
        const int d0 = blockIdx.x * 256;
#pragma unroll
        for (int i = 0; i < 4; i++) {
            const int row = wm + i * 16 + grp;           // local n: 0..127
#pragma unroll
            for (int j = 0; j < 8; j++) {
                const int col = wn + j * 8 + 2 * tig;    // local d: 0..255
                const float b0 = bias[d0 + col], b1 = bias[d0 + col + 1];
                Ts[(col)     * 136 + row]     = __float2half(acc[i][j][0] + b0);
                Ts[(col + 1) * 136 + row]     = __float2half(acc[i][j][1] + b1);
                Ts[(col)     * 136 + row + 8] = __float2half(acc[i][j][2] + b0);
                Ts[(col + 1) * 136 + row + 8] = __float2half(acc[i][j][3] + b1);
            }
        }
        __syncthreads();
        // coalesced write-out: thread t owns d-row t (128 halves = 16 x uint4)
        __half* dst = g_Vth + (size_t)b * DIM * NSEQ + (size_t)(d0 + tid) * NSEQ + n0;
        const uint4* srow = reinterpret_cast<const uint4*>(Ts + (size_t)tid * 136);
#pragma unroll
        for (int i = 0; i < 16; i++)
            reinterpret_cast<uint4*>(dst)[i] = srow[i];
    }
}

// ---------------------------------------------------------------------------
// Kernel 3: scores = mask(QK^T / sqrt(D)) -> fp32 S. grid (8, 16, 8)
// ---------------------------------------------------------------------------
__global__ void __launch_bounds__(256, 1) scores_tc(const int* __restrict__ mask)
{
    const int b = blockIdx.z;
    float acc[4][8][4];
    ACC_INIT(acc);
    gemm_nt_256(g_Qh + (size_t)b * NSEQ * DIM, g_Kh + (size_t)b * NSEQ * DIM,
                DIM, DIM, DIM / KT, acc);

    const float scale = 0.04419417382415922f;  // 1/sqrt(512)
    const int lane = threadIdx.x & 31;
    const int warp = threadIdx.x >> 5;
    const int wm = (warp & 1) * 64;
    const int wn = (warp >> 1) * 64;
    const int grp = lane >> 2, tig = lane & 3;
    const int* mrow = mask + (size_t)b * NSEQ;
    float* C = g_S + (size_t)b * NSEQ * NSEQ;
#pragma unroll
    for (int i = 0; i < 4; i++) {
        const int row = blockIdx.y * 128 + wm + i * 16 + grp;
#pragma unroll
        for (int j = 0; j < 8; j++) {
            const int col = blockIdx.x * 256 + wn + j * 8 + 2 * tig;
            const bool k0 = (mrow[col] == 0);
            const bool k1 = (mrow[col + 1] == 0);
            const float v0 = k0 ? -1e9f : acc[i][j][0] * scale;
            const float v1 = k1 ? -1e9f : acc[i][j][1] * scale;
            const float v2 = k0 ? -1e9f : acc[i][j][2] * scale;
            const float v3 = k1 ? -1e9f : acc[i][j][3] * scale;
            *(float2*)&C[(size_t)row * NSEQ + col]       = make_float2(v0, v1);
            *(float2*)&C[(size_t)(row + 8) * NSEQ + col] = make_float2(v2, v3);
        }
    }
}

// ---------------------------------------------------------------------------
// Kernel 4: row softmax fp32 S -> fp16 P. One block (256 thr) per row. float4 IO.
// ---------------------------------------------------------------------------
__global__ void __launch_bounds__(256) softmax_kernel()
{
    __shared__ float sred[8];
    const float4* r4 = (const float4*)(g_S + (size_t)blockIdx.x * NSEQ);
    uint2* o4 = (uint2*)(g_P + (size_t)blockIdx.x * NSEQ);
    const int tid = threadIdx.x;

    const float4 a = r4[tid];
    const float4 bq = r4[256 + tid];
    float v[8] = {a.x, a.y, a.z, a.w, bq.x, bq.y, bq.z, bq.w};

    float m = v[0];
#pragma unroll
    for (int t = 1; t < 8; t++) m = fmaxf(m, v[t]);
#pragma unroll
    for (int off = 16; off > 0; off >>= 1)
        m = fmaxf(m, __shfl_xor_sync(0xffffffffu, m, off));
    if ((tid & 31) == 0) sred[tid >> 5] = m;
    __syncthreads();
    m = sred[0];
#pragma unroll
    for (int w = 1; w < 8; w++) m = fmaxf(m, sred[w]);

    float s = 0.f;
#pragma unroll
    for (int t = 0; t < 8; t++) {
        v[t] = __expf(v[t] - m);
        s += v[t];
    }
#pragma unroll
    for (int off = 16; off > 0; off >>= 1)
        s += __shfl_xor_sync(0xffffffffu, s, off);
    __syncthreads();
    if ((tid & 31) == 0) sred[tid >> 5] = s;
    __syncthreads();
    s = 0.f;
#pragma unroll
    for (int w = 0; w < 8; w++) s += sred[w];
    const float inv = 1.0f / s;

    o4[tid]       = make_uint2(pk(v[0] * inv, v[1] * inv), pk(v[2] * inv, v[3] * inv));
    o4[256 + tid] = make_uint2(pk(v[4] * inv, v[5] * inv), pk(v[6] * inv, v[7] * inv));
}

// ---------------------------------------------------------------------------
// Kernel 5: O = P @ Vt^T (NT). grid (DIM/256=2, 16, 8)
// ---------------------------------------------------------------------------
__global__ void __launch_bounds__(256, 1) av_tc(float* __restrict__ out)
{
    const int b = blockIdx.z;
    float acc[4][8][4];
    ACC_INIT(acc);
    gemm_nt_256(g_P   + (size_t)b * NSEQ * NSEQ,
                g_Vth + (size_t)b * DIM * NSEQ,
                NSEQ, NSEQ, NSEQ / KT, acc);

    float* C = out + (size_t)b * NSEQ * DIM;
    const int lane = threadIdx.x & 31;
    const int warp = threadIdx.x >> 5;
    const int wm = (warp & 1) * 64;
    const int wn = (warp >> 1) * 64;
    const int grp = lane >> 2, tig = lane & 3;
#pragma unroll
    for (int i = 0; i < 4; i++) {
        const int row = blockIdx.y * 128 + wm + i * 16 + grp;
#pragma unroll
        for (int j = 0; j < 8; j++) {
            const int col = blockIdx.x * 256 + wn + j * 8 + 2 * tig;
            *(float2*)&C[(size_t)row * DIM + col] =
                make_float2(acc[i][j][0], acc[i][j][1]);
            *(float2*)&C[(size_t)(row + 8) * DIM + col] =
                make_float2(acc[i][j][2], acc[i][j][3]);
        }
    }
}

// ---------------------------------------------------------------------------
// Launch
// ---------------------------------------------------------------------------
extern "C" void kernel_launch(void* const* d_in, const int* in_sizes, int n_in,
                              void* d_out, int out_size)
{
    const float* X    = (const float*)d_in[0];
    const int*   mask = (const int*)  d_in[1];
    const float* Wk   = (const float*)d_in[2];
    const float* bk   = (const float*)d_in[3];
    const float* Wq   = (const float*)d_in[4];
    const float* bq   = (const float*)d_in[5];
    const float* Wv   = (const float*)d_in[6];
    const float* bv   = (const float*)d_in[7];
    float* out = (float*)d_out;

    cudaFuncSetAttribute(proj_tc,   cudaFuncAttributeMaxDynamicSharedMemorySize, DYN_SMEM);
    cudaFuncSetAttribute(scores_tc, cudaFuncAttributeMaxDynamicSharedMemorySize, DYN_SMEM);
    cudaFuncSetAttribute(av_tc,     cudaFuncAttributeMaxDynamicSharedMemorySize, DYN_SMEM);

    __half* x_h;
    cudaGetSymbolAddress((void**)&x_h, g_Xh);

    const int nx4 = MTOT * DIM / 4;
    cvt_kernel<<<(nx4 + 255) / 256, 256>>>(X, x_h, nx4);
    cvtw_kernel<<<dim3(DIM * DIM / 4 / 256, 3), 256>>>(Wq, Wk, Wv);

    proj_tc   <<<dim3(DIM / 256, MTOT / 128, 3), 256, DYN_SMEM>>>(bq, bk, bv);
    scores_tc <<<dim3(NSEQ / 256, NSEQ / 128, BB), 256, DYN_SMEM>>>(mask);
    softmax_kernel<<<MTOT, 256>>>();
    av_tc     <<<dim3(DIM / 256, NSEQ / 128, BB), 256, DYN_SMEM>>>(out);
}